// round 14
// baseline (speedup 1.0000x reference)
#include <cuda_runtime.h>
#include <cuda_fp16.h>
#include <math.h>
#include <float.h>
#include <stdint.h>
#include <string.h>

#define B_  4
#define L_  1024
#define D_  512
#define H_  8
#define HD_ 64
#define PROJ_ELEMS (2*B_*H_*L_*HD_)   /* 4,194,304 */
#define MASK_ELEMS ((size_t)B_*L_*L_) /* 4,194,304 */
#define ENC_ELEMS  (8192*512)
#define LOG2E_F 1.4426950408889634f

// producer-split fp16 storage
__device__ unsigned short g_ah[ENC_ELEMS], g_al[ENC_ELEMS];      // [u;e] inputs
__device__ unsigned short g_wth[4*512*512], g_wtl[4*512*512];    // W^T, n-major
__device__ unsigned short g_qh[PROJ_ELEMS], g_ql[PROJ_ELEMS];    // Q hi/lo
__device__ unsigned short g_kh[PROJ_ELEMS];                      // K single fp16
__device__ unsigned short g_vh[PROJ_ELEMS];                      // V single fp16
__device__ unsigned short g_ch[PROJ_ELEMS], g_cl[PROJ_ELEMS];    // ctx hi/lo
__device__ unsigned short g_mb[2*B_*L_*L_];  // fp16 (bias*log2e) | -30000 masked
__device__ int g_mtype;

// ===========================================================================
// helpers
// ===========================================================================
__device__ __forceinline__ uint32_t smem_u32(const void* p) {
    uint32_t a;
    asm("{ .reg .u64 t; cvta.to.shared.u64 t, %1; cvt.u32.u64 %0, t; }"
        : "=r"(a) : "l"(p));
    return a;
}
#define CP_ASYNC16(saddr, gptr) \
    asm volatile("cp.async.ca.shared.global [%0], [%1], 16;" \
                 :: "r"(saddr), "l"(gptr))
#define CP_COMMIT() asm volatile("cp.async.commit_group;" ::: "memory")
#define CP_WAIT0()  asm volatile("cp.async.wait_group 0;" ::: "memory")

__device__ __forceinline__ float ex2f(float x) {
    float r;
    asm("ex2.approx.f32 %0, %1;" : "=f"(r) : "f"(x));
    return r;
}
__device__ __forceinline__ void ldsm_x4(uint32_t& r0, uint32_t& r1,
                                        uint32_t& r2, uint32_t& r3,
                                        uint32_t addr) {
    asm volatile("ldmatrix.sync.aligned.m8n8.x4.shared.b16 {%0,%1,%2,%3}, [%4];"
                 : "=r"(r0), "=r"(r1), "=r"(r2), "=r"(r3) : "r"(addr));
}
__device__ __forceinline__ void ldsm_x4_t(uint32_t& r0, uint32_t& r1,
                                          uint32_t& r2, uint32_t& r3,
                                          uint32_t addr) {
    asm volatile("ldmatrix.sync.aligned.m8n8.x4.trans.shared.b16 {%0,%1,%2,%3}, [%4];"
                 : "=r"(r0), "=r"(r1), "=r"(r2), "=r"(r3) : "r"(addr));
}
__device__ __forceinline__ void mma_f16(float* c, const uint32_t* a,
                                        const uint32_t* b) {
    asm volatile("mma.sync.aligned.m16n8k16.row.col.f32.f16.f16.f32 "
                 "{%0,%1,%2,%3}, {%4,%5,%6,%7}, {%8,%9}, {%0,%1,%2,%3};"
                 : "+f"(c[0]), "+f"(c[1]), "+f"(c[2]), "+f"(c[3])
                 : "r"(a[0]), "r"(a[1]), "r"(a[2]), "r"(a[3]),
                   "r"(b[0]), "r"(b[1]));
}
__device__ __forceinline__ unsigned short f2h_bits(float x) {
    __half h = __float2half_rn(x);
    unsigned short u; memcpy(&u, &h, 2); return u;
}
__device__ __forceinline__ float hbits2f(unsigned short u) {
    __half h; memcpy(&h, &u, 2); return __half2float(h);
}
__device__ __forceinline__ void split2(float x, float y, uint32_t& hi, uint32_t& lo) {
    unsigned short hx = f2h_bits(x), hy = f2h_bits(y);
    unsigned short lx = f2h_bits(x - hbits2f(hx));
    unsigned short ly = f2h_bits(y - hbits2f(hy));
    hi = (uint32_t)hx | ((uint32_t)hy << 16);
    lo = (uint32_t)lx | ((uint32_t)ly << 16);
}
__device__ __forceinline__ uint32_t pack2h(float x, float y) {
    return (uint32_t)f2h_bits(x) | ((uint32_t)f2h_bits(y) << 16);
}
__device__ __forceinline__ float2 h2unpack(uint32_t w) {
    __half2 h; memcpy(&h, &w, 4);
    return __half22float2(h);
}

// ===========================================================================
// Mask dtype detection
// ===========================================================================
__global__ void mask_detect_kernel(const unsigned int* __restrict__ m)
{
    __shared__ int viol[3];
    if (threadIdx.x < 3) viol[threadIdx.x] = 0;
    __syncthreads();
    int v0 = 0, v1 = 0, v2 = 0;
    for (int i = threadIdx.x; i < 16384; i += 256) {
        unsigned w = m[i];
        if (w > 1u) v0 = 1;
        if (w != 0u && w != 0x3F800000u) v1 = 1;
        if (w != 0u && w != 0x3F800000u && w != 0x00003F80u && w != 0x3F803F80u) v2 = 1;
    }
    if (v0) atomicOr(&viol[0], 1);
    if (v1) atomicOr(&viol[1], 1);
    if (v2) atomicOr(&viol[2], 1);
    __syncthreads();
    if (threadIdx.x == 0) {
        int t;
        if      (!viol[0]) t = 1;
        else if (!viol[1]) t = 2;
        else if (!viol[2]) t = 3;
        else               t = 0;
        g_mtype = t;
    }
}

// ===========================================================================
// Fused prep: blocks [0,2048) maskbias, [2048,4096) enc split, [4096,5120) wt.
// ===========================================================================
__global__ __launch_bounds__(256) void prep_kernel(
    const float* __restrict__ lb,
    const float* __restrict__ wp, const float* __restrict__ bp,
    const void* __restrict__ ue, const void* __restrict__ eu,
    const float* __restrict__ u, const float* __restrict__ e,
    const float* __restrict__ wq, const float* __restrict__ wk,
    const float* __restrict__ wv, const float* __restrict__ wo)
{
    __shared__ float s[32][33];
    int bx = blockIdx.x;
    int tid = threadIdx.x;
    int tx = tid & 31, ty = tid >> 5;

    if (bx < 2048) {
        int dir = bx >> 10;
        int q0 = ((bx >> 5) & 31) * 32;
        int k0 = (bx & 31) * 32;
        int mt = g_mtype;
        float w = wp[0] * LOG2E_F, bb = bp[0] * LOG2E_F;
        const void* msk = dir ? eu : ue;
        unsigned short* dst = g_mb + (size_t)dir * MASK_ELEMS;

        if (dir == 1) {
            #pragma unroll
            for (int i = ty; i < 32; i += 8)
                s[i][tx] = lb[(size_t)(k0+i)*L_ + q0 + tx];
            __syncthreads();
        }
        unsigned short mk = f2h_bits(-30000.0f);
        #pragma unroll
        for (int i = ty; i < 32; i += 8) {
            float bias;
            if (dir == 0) bias = fmaf(w, lb[(size_t)(q0+i)*L_ + k0 + tx], bb);
            else          bias = fmaf(w, s[tx][i], bb);
            unsigned short bh = f2h_bits(bias);
            size_t rowoff = (size_t)(q0+i)*L_ + k0 + tx;
            #pragma unroll
            for (int b = 0; b < B_; b++) {
                size_t idx = ((size_t)b << 20) + rowoff;
                bool mv;
                if      (mt == 1) mv = ((const int*)msk)[idx] != 0;
                else if (mt == 2) mv = ((const float*)msk)[idx] != 0.f;
                else if (mt == 3) mv = ((const unsigned short*)msk)[idx] != 0;
                else              mv = ((const unsigned char*)msk)[idx] != 0;
                dst[idx] = mv ? bh : mk;
            }
        }
    } else if (bx < 4096) {
        int idx = bx - 2048;
        int z = idx >> 10, blk = idx & 1023;
        const float* src = z ? e : u;
        size_t base4 = (size_t)z * (4096*512/4);
        size_t stride = 1024u * 256u;
        for (size_t i4 = (size_t)blk*256 + tid; i4 < 4096*512/4; i4 += stride) {
            float4 v = ((const float4*)src)[i4];
            uint32_t h01, l01, h23, l23;
            split2(v.x, v.y, h01, l01);
            split2(v.z, v.w, h23, l23);
            ((uint2*)g_ah)[base4 + i4] = make_uint2(h01, h23);
            ((uint2*)g_al)[base4 + i4] = make_uint2(l01, l23);
        }
    } else {
        int idx = bx - 4096;
        int z = idx >> 8, by = (idx >> 4) & 15, bxx = idx & 15;
        const float* src = (z == 0) ? wq : (z == 1) ? wk : (z == 2) ? wv : wo;
        int x  = bxx*32 + tx;
        int y0 = by*32;
        #pragma unroll
        for (int i = ty; i < 32; i += 8)
            s[i][tx] = src[(size_t)(y0+i)*512 + x];
        __syncthreads();
        size_t base = (size_t)z * 512*512;
        int ko = y0 + tx;
        #pragma unroll
        for (int i = ty; i < 32; i += 8) {
            float v = s[tx][i];
            unsigned short h = f2h_bits(v);
            unsigned short l = f2h_bits(v - hbits2f(h));
            size_t widx = base + (size_t)(bxx*32+i)*512 + ko;
            g_wth[widx] = h;
            g_wtl[widx] = l;
        }
    }
}

// ===========================================================================
// GEMM: 128M x 64N, K chunks 64, cp.async double-buffered (unchanged).
// ===========================================================================
#define GM_BUF  55296
#define GM_AH   0
#define GM_AL   18432
#define GM_BH   36864
#define GM_BL   46080
#define GM_SMEM 110592

__global__ __launch_bounds__(256) void gemm_mma_kernel(
    const float* __restrict__ bq, const float* __restrict__ bk,
    const float* __restrict__ bv, const float* __restrict__ bo,
    float* __restrict__ outp, int modebase)
{
    extern __shared__ __align__(16) unsigned char smem[];
    uint32_t sbase = smem_u32(smem);

    int tid = threadIdx.x;
    int wid = tid >> 5, lane = tid & 31;
    int wm = wid & 3, wn = wid >> 2;

    int mode = modebase + blockIdx.z;
    const float* bias;
    if      (mode == 0) bias = bq;
    else if (mode == 1) bias = bk;
    else if (mode == 2) bias = bv;
    else                bias = bo;

    const unsigned short* Ah = (mode < 3) ? g_ah : g_ch;
    const unsigned short* Al = (mode < 3) ? g_al : g_cl;
    int widx = (mode < 3) ? mode : 3;
    const unsigned short* Bh = g_wth + (size_t)widx*512*512;
    const unsigned short* Bl = g_wtl + (size_t)widx*512*512;
    bool three = (mode == 0);

    int n0   = blockIdx.x * 64;
    int row0 = blockIdx.y * 128;

    float acc[2][4][4];
    #pragma unroll
    for (int mi = 0; mi < 2; mi++)
        #pragma unroll
        for (int ni = 0; ni < 4; ni++)
            #pragma unroll
            for (int c = 0; c < 4; c++) acc[mi][ni][c] = 0.f;

    auto issue_chunk = [&](int kb, uint32_t bufo) {
        int kbase = kb * 64;
        #pragma unroll
        for (int i = 0; i < 8; i++) {
            int idx = i*256 + tid;
            int a = idx >> 10;
            int rem = idx & 1023;
            int row = rem >> 3, q8 = rem & 7;
            const unsigned short* srcp = a ? Al : Ah;
            CP_ASYNC16(sbase + bufo + (a ? GM_AL : GM_AH) + row*144 + q8*16,
                       &srcp[(size_t)(row0+row)*512 + kbase + q8*8]);
        }
        #pragma unroll
        for (int i = 0; i < 2; i++) {
            int idx = i*256 + tid;
            int row = idx >> 3, q8 = idx & 7;
            CP_ASYNC16(sbase + bufo + GM_BH + row*144 + q8*16,
                       &Bh[(size_t)(n0+row)*512 + kbase + q8*8]);
        }
        if (three) {
            #pragma unroll
            for (int i = 0; i < 2; i++) {
                int idx = i*256 + tid;
                int row = idx >> 3, q8 = idx & 7;
                CP_ASYNC16(sbase + bufo + GM_BL + row*144 + q8*16,
                           &Bl[(size_t)(n0+row)*512 + kbase + q8*8]);
            }
        }
        CP_COMMIT();
    };

    issue_chunk(0, 0);

    for (int kb = 0; kb < 8; kb++) {
        uint32_t bufo = (kb & 1) ? GM_BUF : 0;
        CP_WAIT0();
        __syncthreads();
        if (kb + 1 < 8)
            issue_chunk(kb + 1, ((kb + 1) & 1) ? GM_BUF : 0);

        #pragma unroll
        for (int ks = 0; ks < 4; ks++) {
            uint32_t a_hi[2][4], a_lo[2][4], b_hi[8], b_lo[8];
            #pragma unroll
            for (int mi = 0; mi < 2; mi++) {
                int row = wm*32 + mi*16 + (lane & 15);
                int kcol = ks*16 + ((lane >> 4) << 3);
                uint32_t off = bufo + (uint32_t)(row*144 + kcol*2);
                ldsm_x4(a_hi[mi][0], a_hi[mi][1], a_hi[mi][2], a_hi[mi][3],
                        sbase + GM_AH + off);
                ldsm_x4(a_lo[mi][0], a_lo[mi][1], a_lo[mi][2], a_lo[mi][3],
                        sbase + GM_AL + off);
            }
            #pragma unroll
            for (int g = 0; g < 2; g++) {
                int rr = lane & 7;
                int hk = (lane >> 3) & 1;
                int hn = (lane >> 4) & 1;
                int nrow = wn*32 + g*16 + hn*8 + rr;
                int kcol = ks*16 + hk*8;
                uint32_t off = bufo + (uint32_t)(nrow*144 + kcol*2);
                ldsm_x4(b_hi[g*4+0], b_hi[g*4+1], b_hi[g*4+2], b_hi[g*4+3],
                        sbase + GM_BH + off);
                if (three)
                    ldsm_x4(b_lo[g*4+0], b_lo[g*4+1], b_lo[g*4+2], b_lo[g*4+3],
                            sbase + GM_BL + off);
            }
            #pragma unroll
            for (int mi = 0; mi < 2; mi++)
                #pragma unroll
                for (int ni = 0; ni < 4; ni++)
                    mma_f16(acc[mi][ni], a_hi[mi], &b_hi[ni*2]);
            #pragma unroll
            for (int mi = 0; mi < 2; mi++)
                #pragma unroll
                for (int ni = 0; ni < 4; ni++)
                    mma_f16(acc[mi][ni], a_lo[mi], &b_hi[ni*2]);
            if (three) {
                #pragma unroll
                for (int mi = 0; mi < 2; mi++)
                    #pragma unroll
                    for (int ni = 0; ni < 4; ni++)
                        mma_f16(acc[mi][ni], a_hi[mi], &b_lo[ni*2]);
            }
        }
    }

    float scale = (mode == 0) ? 0.125f * LOG2E_F : 1.f;
    #pragma unroll
    for (int mi = 0; mi < 2; mi++) {
        #pragma unroll
        for (int ni = 0; ni < 4; ni++) {
            int nl = wn*32 + ni*8 + (lane & 3)*2;
            float b0 = bias[n0 + nl], b1 = bias[n0 + nl + 1];
            #pragma unroll
            for (int half = 0; half < 2; half++) {
                int m = row0 + wm*32 + mi*16 + (lane >> 2) + half*8;
                float ox = (acc[mi][ni][half*2+0] + b0) * scale;
                float oy = (acc[mi][ni][half*2+1] + b1) * scale;
                if (mode < 3) {
                    int enc = m >> 12, b = (m >> 10) & 3, l = m & 1023;
                    int h = n0 >> 6;
                    size_t idx = ((((size_t)(enc*B_ + b))*H_ + h)*L_ + l)*HD_ + nl;
                    if (mode == 0) {
                        uint32_t hi, lo; split2(ox, oy, hi, lo);
                        *(uint32_t*)&g_qh[idx] = hi;
                        *(uint32_t*)&g_ql[idx] = lo;
                    } else if (mode == 1) {
                        *(uint32_t*)&g_kh[idx] = pack2h(ox, oy);
                    } else {
                        *(uint32_t*)&g_vh[idx] = pack2h(ox, oy);
                    }
                } else {
                    float2 o; o.x = ox; o.y = oy;
                    *(float2*)&outp[(size_t)m*D_ + nl + n0] = o;
                }
            }
        }
    }
}

// ===========================================================================
// Flash attention v3: 32 q-rows/warp, 128 q-rows/CTA, 4 warps; ALL Q frags
// reloaded from smem per k-step (register budget 170 -> 3 CTAs/SM).
//   grid (8 qtiles, 32 b*h, 2 dirs), 128 threads.
// KV ring 2 x 18432 at [0, 36864); Q (QH+QL, 128 rows) at 36864..73728.
// ===========================================================================
#define AT_BUF  18432
#define AT_KH   0
#define AT_VH   9216
#define AT_Q    36864
#define AT_QL   (36864 + 18432)
#define AT_SMEM 73728

__global__ __launch_bounds__(128, 3) void attn_mma_kernel()
{
    extern __shared__ __align__(16) unsigned char smem[];
    uint32_t sbase = smem_u32(smem);

    int tid = threadIdx.x;
    int wid = tid >> 5, lane = tid & 31;
    int r = lane >> 2, cq = lane & 3;

    int qt = blockIdx.x, bh = blockIdx.y, dir = blockIdx.z;
    int b = bh >> 3, h = bh & 7;
    int enc_q = dir, enc_kv = 1 - dir;

    size_t qoff  = ((size_t)((enc_q *B_ + b)*H_ + h))*L_*HD_;
    size_t kvoff = ((size_t)((enc_kv*B_ + b)*H_ + h))*L_*HD_;
    const unsigned short* Kh = g_kh + kvoff;
    const unsigned short* Vh = g_vh + kvoff;
    const unsigned short* mb = g_mb + ((size_t)dir*B_ + b)*L_*L_;
    int q0 = qt * 128;

    // ---- Q cp.async: 128 rows x 8 uint4 x 2 arrays = 2048 / 128 = 16 iters
    {
        const unsigned short* Qh = g_qh + qoff;
        const unsigned short* Ql = g_ql + qoff;
        #pragma unroll
        for (int i = 0; i < 16; i++) {
            int idx = i*128 + tid;
            int a = idx >> 10;
            int rem = idx & 1023;
            int row = rem >> 3, q8 = rem & 7;
            const unsigned short* srcp = a ? Ql : Qh;
            CP_ASYNC16(sbase + (a ? AT_QL : AT_Q) + row*144 + q8*16,
                       &srcp[(size_t)(q0+row)*HD_ + q8*8]);
        }
    }
    CP_COMMIT();

    auto issue_kv = [&](int t, uint32_t bufo) {
        int k0 = t * 64;
        #pragma unroll
        for (int i = 0; i < 8; i++) {
            int idx = i*128 + tid;
            int a = idx >> 9;
            int rem = idx & 511;
            int row = rem >> 3, q8 = rem & 7;
            const unsigned short* srcp = a ? Vh : Kh;
            int dsto = a ? AT_VH : AT_KH;
            CP_ASYNC16(sbase + bufo + dsto + row*144 + q8*16,
                       &srcp[(size_t)(k0+row)*HD_ + q8*8]);
        }
        CP_COMMIT();
    };

    issue_kv(0, 0);

    float o_acc[2][8][4];
    #pragma unroll
    for (int mt = 0; mt < 2; mt++)
        #pragma unroll
        for (int nt = 0; nt < 8; nt++)
            #pragma unroll
            for (int c = 0; c < 4; c++) o_acc[mt][nt][c] = 0.f;
    float mreg[2][2], lreg[2][2];
    #pragma unroll
    for (int mt = 0; mt < 2; mt++) {
        mreg[mt][0] = -3.0e38f; mreg[mt][1] = -3.0e38f;
        lreg[mt][0] = 0.f;      lreg[mt][1] = 0.f;
    }

    int qgw = q0 + wid*32 + r;

    for (int t = 0; t < 16; t++) {
        int k0 = t * 64;
        uint32_t bufo = (t & 1) ? AT_BUF : 0;
        CP_WAIT0();
        __syncthreads();
        if (t + 1 < 16)
            issue_kv(t + 1, ((t + 1) & 1) ? AT_BUF : 0);

        // ---- S = Q K^T : Q frags loaded from smem per ks; B shared by mt ----
        float s_acc[2][8][4];
        #pragma unroll
        for (int mt = 0; mt < 2; mt++)
            #pragma unroll
            for (int nt = 0; nt < 8; nt++)
                #pragma unroll
                for (int c = 0; c < 4; c++) s_acc[mt][nt][c] = 0.f;

        #pragma unroll
        for (int ks = 0; ks < 4; ks++) {
            uint32_t aq_h[2][4], aq_l[2][4];
            #pragma unroll
            for (int mt = 0; mt < 2; mt++) {
                int row = wid*32 + mt*16 + (lane & 15);
                int kcol = ks*16 + ((lane >> 4) << 3);
                uint32_t qoff2 = (uint32_t)(row*144 + kcol*2);
                ldsm_x4(aq_h[mt][0], aq_h[mt][1], aq_h[mt][2], aq_h[mt][3],
                        sbase + AT_Q + qoff2);
                ldsm_x4(aq_l[mt][0], aq_l[mt][1], aq_l[mt][2], aq_l[mt][3],
                        sbase + AT_QL + qoff2);
            }
            #pragma unroll
            for (int g = 0; g < 4; g++) {
                uint32_t bk[4];
                int rr = lane & 7;
                int hk = (lane >> 3) & 1;
                int hn = (lane >> 4) & 1;
                int nrow = g*16 + hn*8 + rr;
                int kcol = ks*16 + hk*8;
                uint32_t off = bufo + (uint32_t)(nrow*144 + kcol*2);
                ldsm_x4(bk[0], bk[1], bk[2], bk[3], sbase + AT_KH + off);
                int n0t = g*2, n1t = g*2 + 1;
                #pragma unroll
                for (int mt = 0; mt < 2; mt++) {
                    mma_f16(s_acc[mt][n0t], aq_h[mt], &bk[0]);
                    mma_f16(s_acc[mt][n1t], aq_h[mt], &bk[2]);
                    mma_f16(s_acc[mt][n0t], aq_l[mt], &bk[0]);
                    mma_f16(s_acc[mt][n1t], aq_l[mt], &bk[2]);
                }
            }
        }

        // ---- mask+bias add + online softmax per m-tile ----
        #pragma unroll
        for (int mt = 0; mt < 2; mt++) {
            const unsigned short* mb0 = mb + (size_t)(qgw + mt*16)*L_ + k0 + cq*2;
            const unsigned short* mb1 = mb0 + 8*L_;
            #pragma unroll
            for (int nt = 0; nt < 8; nt++) {
                float2 b0v = h2unpack(*(const uint32_t*)&mb0[nt*8]);
                float2 b1v = h2unpack(*(const uint32_t*)&mb1[nt*8]);
                s_acc[mt][nt][0] += b0v.x;
                s_acc[mt][nt][1] += b0v.y;
                s_acc[mt][nt][2] += b1v.x;
                s_acc[mt][nt][3] += b1v.y;
            }

            float mx0 = -3.0e38f, mx1 = -3.0e38f;
            #pragma unroll
            for (int nt = 0; nt < 8; nt++) {
                mx0 = fmaxf(mx0, fmaxf(s_acc[mt][nt][0], s_acc[mt][nt][1]));
                mx1 = fmaxf(mx1, fmaxf(s_acc[mt][nt][2], s_acc[mt][nt][3]));
            }
            mx0 = fmaxf(mx0, __shfl_xor_sync(0xffffffffu, mx0, 1));
            mx0 = fmaxf(mx0, __shfl_xor_sync(0xffffffffu, mx0, 2));
            mx1 = fmaxf(mx1, __shfl_xor_sync(0xffffffffu, mx1, 1));
            mx1 = fmaxf(mx1, __shfl_xor_sync(0xffffffffu, mx1, 2));

            float mn0 = fmaxf(mreg[mt][0], mx0);
            float mn1 = fmaxf(mreg[mt][1], mx1);
            float c0 = ex2f(mreg[mt][0] - mn0);
            float c1 = ex2f(mreg[mt][1] - mn1);
            mreg[mt][0] = mn0; mreg[mt][1] = mn1;

            float rs0 = 0.f, rs1 = 0.f;
            #pragma unroll
            for (int nt = 0; nt < 8; nt++) {
                s_acc[mt][nt][0] = ex2f(s_acc[mt][nt][0] - mn0); rs0 += s_acc[mt][nt][0];
                s_acc[mt][nt][1] = ex2f(s_acc[mt][nt][1] - mn0); rs0 += s_acc[mt][nt][1];
                s_acc[mt][nt][2] = ex2f(s_acc[mt][nt][2] - mn1); rs1 += s_acc[mt][nt][2];
                s_acc[mt][nt][3] = ex2f(s_acc[mt][nt][3] - mn1); rs1 += s_acc[mt][nt][3];
            }
            rs0 += __shfl_xor_sync(0xffffffffu, rs0, 1);
            rs0 += __shfl_xor_sync(0xffffffffu, rs0, 2);
            rs1 += __shfl_xor_sync(0xffffffffu, rs1, 1);
            rs1 += __shfl_xor_sync(0xffffffffu, rs1, 2);
            lreg[mt][0] = lreg[mt][0]*c0 + rs0;
            lreg[mt][1] = lreg[mt][1]*c1 + rs1;

            #pragma unroll
            for (int nt = 0; nt < 8; nt++) {
                o_acc[mt][nt][0] *= c0; o_acc[mt][nt][1] *= c0;
                o_acc[mt][nt][2] *= c1; o_acc[mt][nt][3] *= c1;
            }
        }

        // ---- O += P V : shared V-frags across m-tiles ----
        #pragma unroll
        for (int ks = 0; ks < 4; ks++) {
            int t0 = 2*ks, t1 = 2*ks + 1;
            uint32_t ap[2][4];
            #pragma unroll
            for (int mt = 0; mt < 2; mt++) {
                ap[mt][0] = pack2h(s_acc[mt][t0][0], s_acc[mt][t0][1]);
                ap[mt][1] = pack2h(s_acc[mt][t0][2], s_acc[mt][t0][3]);
                ap[mt][2] = pack2h(s_acc[mt][t1][0], s_acc[mt][t1][1]);
                ap[mt][3] = pack2h(s_acc[mt][t1][2], s_acc[mt][t1][3]);
            }
            #pragma unroll
            for (int g = 0; g < 4; g++) {
                uint32_t bv[4];
                int kk  = ks*16 + ((lane >> 3) & 1)*8 + (lane & 7);
                int hdo = g*16 + ((lane >> 4) & 1)*8;
                uint32_t off = bufo + (uint32_t)(kk*144 + hdo*2);
                ldsm_x4_t(bv[0], bv[1], bv[2], bv[3], sbase + AT_VH + off);
                int n0t = g*2, n1t = g*2 + 1;
                #pragma unroll
                for (int mt = 0; mt < 2; mt++) {
                    mma_f16(o_acc[mt][n0t], ap[mt], &bv[0]);
                    mma_f16(o_acc[mt][n1t], ap[mt], &bv[2]);
                }
            }
        }
    }

    // ---- finalize: ctx = O/l as fp16 hi/lo ----
    #pragma unroll
    for (int mt = 0; mt < 2; mt++) {
        float inv0 = 1.f / lreg[mt][0];
        float inv1 = 1.f / lreg[mt][1];
        int row0g = qgw + mt*16;
        size_t base0 = ((size_t)(enc_q*B_ + b)*L_ + row0g)*D_ + h*64 + cq*2;
        size_t base1 = ((size_t)(enc_q*B_ + b)*L_ + row0g + 8)*D_ + h*64 + cq*2;
        #pragma unroll
        for (int nt = 0; nt < 8; nt++) {
            uint32_t hi0, lo0, hi1, lo1;
            split2(o_acc[mt][nt][0]*inv0, o_acc[mt][nt][1]*inv0, hi0, lo0);
            split2(o_acc[mt][nt][2]*inv1, o_acc[mt][nt][3]*inv1, hi1, lo1);
            *(uint32_t*)&g_ch[base0 + nt*8] = hi0;
            *(uint32_t*)&g_cl[base0 + nt*8] = lo0;
            *(uint32_t*)&g_ch[base1 + nt*8] = hi1;
            *(uint32_t*)&g_cl[base1 + nt*8] = lo1;
        }
    }
}

// ---------------------------------------------------------------------------
extern "C" void kernel_launch(void* const* d_in, const int* in_sizes, int n_in,
                              void* d_out, int out_size)
{
    const float* u_enc     = (const float*)d_in[0];
    const float* e_enc     = (const float*)d_in[1];
    const float* logit_bpp = (const float*)d_in[2];
    const void*  ue_mask   = d_in[3];
    const void*  eu_mask   = d_in[4];
    const float* wq_k = (const float*)d_in[5];
    const float* wq_b = (const float*)d_in[6];
    const float* wk_k = (const float*)d_in[7];
    const float* wk_b = (const float*)d_in[8];
    const float* wv_k = (const float*)d_in[9];
    const float* wv_b = (const float*)d_in[10];
    const float* wo_k = (const float*)d_in[11];
    const float* wo_b = (const float*)d_in[12];
    const float* bpp_w = (const float*)d_in[13];
    const float* bpp_b = (const float*)d_in[14];
    float* out = (float*)d_out;

    cudaFuncSetAttribute((const void*)attn_mma_kernel,
                         cudaFuncAttributeMaxDynamicSharedMemorySize, AT_SMEM);
    cudaFuncSetAttribute((const void*)gemm_mma_kernel,
                         cudaFuncAttributeMaxDynamicSharedMemorySize, GM_SMEM);

    // 0) mask dtype detection
    mask_detect_kernel<<<1, 256>>>((const unsigned int*)ue_mask);
    // 1) fused prep
    prep_kernel<<<5120, 256>>>(logit_bpp, bpp_w, bpp_b, ue_mask, eu_mask,
                               u_enc, e_enc, wq_k, wk_k, wv_k, wo_k);
    // 2) fused QKV projections
    gemm_mma_kernel<<<dim3(8, 64, 3), 256, GM_SMEM>>>(wq_b, wk_b, wv_b, wo_b,
                                                      nullptr, 0);
    // 3) fused attention (128 q-rows/CTA, 3 CTAs/SM target)
    attn_mma_kernel<<<dim3(8, 32, 2), 128, AT_SMEM>>>();
    // 4) output projection -> d_out
    gemm_mma_kernel<<<dim3(8, 64, 1), 256, GM_SMEM>>>(wq_b, wk_b, wv_b, wo_b,
                                                      out, 3);
}

// round 15
// speedup vs baseline: 1.1616x; 1.1616x over previous
#include <cuda_runtime.h>
#include <cuda_fp16.h>
#include <math.h>
#include <float.h>
#include <stdint.h>
#include <string.h>

#define B_  4
#define L_  1024
#define D_  512
#define H_  8
#define HD_ 64
#define PROJ_ELEMS (2*B_*H_*L_*HD_)   /* 4,194,304 */
#define MASK_ELEMS ((size_t)B_*L_*L_) /* 4,194,304 */
#define ENC_ELEMS  (8192*512)
#define LOG2E_F 1.4426950408889634f

// producer-split fp16 storage
__device__ unsigned short g_ah[ENC_ELEMS], g_al[ENC_ELEMS];      // [u;e] inputs
__device__ unsigned short g_wth[4*512*512], g_wtl[4*512*512];    // W^T, n-major
__device__ unsigned short g_qh[PROJ_ELEMS], g_ql[PROJ_ELEMS];    // Q hi/lo
__device__ unsigned short g_kh[PROJ_ELEMS];                      // K single fp16
__device__ unsigned short g_vh[PROJ_ELEMS];                      // V single fp16
__device__ unsigned short g_ch[PROJ_ELEMS], g_cl[PROJ_ELEMS];    // ctx hi/lo
__device__ unsigned short g_mb[2*B_*L_*L_];  // fp16 (bias*log2e) | -30000 masked
__device__ int g_mtype;

// ===========================================================================
// helpers
// ===========================================================================
__device__ __forceinline__ uint32_t smem_u32(const void* p) {
    uint32_t a;
    asm("{ .reg .u64 t; cvta.to.shared.u64 t, %1; cvt.u32.u64 %0, t; }"
        : "=r"(a) : "l"(p));
    return a;
}
#define CP_ASYNC16(saddr, gptr) \
    asm volatile("cp.async.ca.shared.global [%0], [%1], 16;" \
                 :: "r"(saddr), "l"(gptr))
#define CP_COMMIT() asm volatile("cp.async.commit_group;" ::: "memory")
#define CP_WAIT0()  asm volatile("cp.async.wait_group 0;" ::: "memory")

__device__ __forceinline__ float ex2f(float x) {
    float r;
    asm("ex2.approx.f32 %0, %1;" : "=f"(r) : "f"(x));
    return r;
}
__device__ __forceinline__ void ldsm_x4(uint32_t& r0, uint32_t& r1,
                                        uint32_t& r2, uint32_t& r3,
                                        uint32_t addr) {
    asm volatile("ldmatrix.sync.aligned.m8n8.x4.shared.b16 {%0,%1,%2,%3}, [%4];"
                 : "=r"(r0), "=r"(r1), "=r"(r2), "=r"(r3) : "r"(addr));
}
__device__ __forceinline__ void ldsm_x4_t(uint32_t& r0, uint32_t& r1,
                                          uint32_t& r2, uint32_t& r3,
                                          uint32_t addr) {
    asm volatile("ldmatrix.sync.aligned.m8n8.x4.trans.shared.b16 {%0,%1,%2,%3}, [%4];"
                 : "=r"(r0), "=r"(r1), "=r"(r2), "=r"(r3) : "r"(addr));
}
__device__ __forceinline__ void mma_f16(float* c, const uint32_t* a,
                                        const uint32_t* b) {
    asm volatile("mma.sync.aligned.m16n8k16.row.col.f32.f16.f16.f32 "
                 "{%0,%1,%2,%3}, {%4,%5,%6,%7}, {%8,%9}, {%0,%1,%2,%3};"
                 : "+f"(c[0]), "+f"(c[1]), "+f"(c[2]), "+f"(c[3])
                 : "r"(a[0]), "r"(a[1]), "r"(a[2]), "r"(a[3]),
                   "r"(b[0]), "r"(b[1]));
}
__device__ __forceinline__ unsigned short f2h_bits(float x) {
    __half h = __float2half_rn(x);
    unsigned short u; memcpy(&u, &h, 2); return u;
}
__device__ __forceinline__ float hbits2f(unsigned short u) {
    __half h; memcpy(&h, &u, 2); return __half2float(h);
}
__device__ __forceinline__ void split2(float x, float y, uint32_t& hi, uint32_t& lo) {
    unsigned short hx = f2h_bits(x), hy = f2h_bits(y);
    unsigned short lx = f2h_bits(x - hbits2f(hx));
    unsigned short ly = f2h_bits(y - hbits2f(hy));
    hi = (uint32_t)hx | ((uint32_t)hy << 16);
    lo = (uint32_t)lx | ((uint32_t)ly << 16);
}
__device__ __forceinline__ uint32_t pack2h(float x, float y) {
    return (uint32_t)f2h_bits(x) | ((uint32_t)f2h_bits(y) << 16);
}
__device__ __forceinline__ float2 h2unpack(uint32_t w) {
    __half2 h; memcpy(&h, &w, 4);
    return __half22float2(h);
}

// ===========================================================================
// Mask dtype detection
// ===========================================================================
__global__ void mask_detect_kernel(const unsigned int* __restrict__ m)
{
    __shared__ int viol[3];
    if (threadIdx.x < 3) viol[threadIdx.x] = 0;
    __syncthreads();
    int v0 = 0, v1 = 0, v2 = 0;
    for (int i = threadIdx.x; i < 16384; i += 256) {
        unsigned w = m[i];
        if (w > 1u) v0 = 1;
        if (w != 0u && w != 0x3F800000u) v1 = 1;
        if (w != 0u && w != 0x3F800000u && w != 0x00003F80u && w != 0x3F803F80u) v2 = 1;
    }
    if (v0) atomicOr(&viol[0], 1);
    if (v1) atomicOr(&viol[1], 1);
    if (v2) atomicOr(&viol[2], 1);
    __syncthreads();
    if (threadIdx.x == 0) {
        int t;
        if      (!viol[0]) t = 1;
        else if (!viol[1]) t = 2;
        else if (!viol[2]) t = 3;
        else               t = 0;
        g_mtype = t;
    }
}

// ===========================================================================
// Fused prep: blocks [0,2048) maskbias, [2048,4096) enc split, [4096,5120) wt.
// ===========================================================================
__global__ __launch_bounds__(256) void prep_kernel(
    const float* __restrict__ lb,
    const float* __restrict__ wp, const float* __restrict__ bp,
    const void* __restrict__ ue, const void* __restrict__ eu,
    const float* __restrict__ u, const float* __restrict__ e,
    const float* __restrict__ wq, const float* __restrict__ wk,
    const float* __restrict__ wv, const float* __restrict__ wo)
{
    __shared__ float s[32][33];
    int bx = blockIdx.x;
    int tid = threadIdx.x;
    int tx = tid & 31, ty = tid >> 5;

    if (bx < 2048) {
        int dir = bx >> 10;
        int q0 = ((bx >> 5) & 31) * 32;
        int k0 = (bx & 31) * 32;
        int mt = g_mtype;
        float w = wp[0] * LOG2E_F, bb = bp[0] * LOG2E_F;
        const void* msk = dir ? eu : ue;
        unsigned short* dst = g_mb + (size_t)dir * MASK_ELEMS;

        if (dir == 1) {
            #pragma unroll
            for (int i = ty; i < 32; i += 8)
                s[i][tx] = lb[(size_t)(k0+i)*L_ + q0 + tx];
            __syncthreads();
        }
        unsigned short mk = f2h_bits(-30000.0f);
        #pragma unroll
        for (int i = ty; i < 32; i += 8) {
            float bias;
            if (dir == 0) bias = fmaf(w, lb[(size_t)(q0+i)*L_ + k0 + tx], bb);
            else          bias = fmaf(w, s[tx][i], bb);
            unsigned short bh = f2h_bits(bias);
            size_t rowoff = (size_t)(q0+i)*L_ + k0 + tx;
            #pragma unroll
            for (int b = 0; b < B_; b++) {
                size_t idx = ((size_t)b << 20) + rowoff;
                bool mv;
                if      (mt == 1) mv = ((const int*)msk)[idx] != 0;
                else if (mt == 2) mv = ((const float*)msk)[idx] != 0.f;
                else if (mt == 3) mv = ((const unsigned short*)msk)[idx] != 0;
                else              mv = ((const unsigned char*)msk)[idx] != 0;
                dst[idx] = mv ? bh : mk;
            }
        }
    } else if (bx < 4096) {
        int idx = bx - 2048;
        int z = idx >> 10, blk = idx & 1023;
        const float* src = z ? e : u;
        size_t base4 = (size_t)z * (4096*512/4);
        size_t stride = 1024u * 256u;
        for (size_t i4 = (size_t)blk*256 + tid; i4 < 4096*512/4; i4 += stride) {
            float4 v = ((const float4*)src)[i4];
            uint32_t h01, l01, h23, l23;
            split2(v.x, v.y, h01, l01);
            split2(v.z, v.w, h23, l23);
            ((uint2*)g_ah)[base4 + i4] = make_uint2(h01, h23);
            ((uint2*)g_al)[base4 + i4] = make_uint2(l01, l23);
        }
    } else {
        int idx = bx - 4096;
        int z = idx >> 8, by = (idx >> 4) & 15, bxx = idx & 15;
        const float* src = (z == 0) ? wq : (z == 1) ? wk : (z == 2) ? wv : wo;
        int x  = bxx*32 + tx;
        int y0 = by*32;
        #pragma unroll
        for (int i = ty; i < 32; i += 8)
            s[i][tx] = src[(size_t)(y0+i)*512 + x];
        __syncthreads();
        size_t base = (size_t)z * 512*512;
        int ko = y0 + tx;
        #pragma unroll
        for (int i = ty; i < 32; i += 8) {
            float v = s[tx][i];
            unsigned short h = f2h_bits(v);
            unsigned short l = f2h_bits(v - hbits2f(h));
            size_t widx = base + (size_t)(bxx*32+i)*512 + ko;
            g_wth[widx] = h;
            g_wtl[widx] = l;
        }
    }
}

// ===========================================================================
// Fused QKV GEMM: one CTA computes Q (3-term), K (2-term), V (2-term) for a
// 128M x 64N tile, sharing the A tile + A fragments across all 7 passes.
//   grid (8, 64), 256 threads (8 warps 4x2). K chunks of 64, double-buffered.
// Stage: AH 0, AL 18432, BQH 36864, BQL 46080, BKH 55296, BVH 64512; 73728.
// ===========================================================================
#define QG_BUF  73728
#define QG_AH   0
#define QG_AL   18432
#define QG_BQH  36864
#define QG_BQL  46080
#define QG_BKH  55296
#define QG_BVH  64512
#define QG_SMEM 147456

__global__ __launch_bounds__(256) void qkv_mma_kernel(
    const float* __restrict__ bq, const float* __restrict__ bk,
    const float* __restrict__ bv)
{
    extern __shared__ __align__(16) unsigned char smem[];
    uint32_t sbase = smem_u32(smem);

    int tid = threadIdx.x;
    int wid = tid >> 5, lane = tid & 31;
    int wm = wid & 3, wn = wid >> 2;

    const unsigned short* Bqh = g_wth;
    const unsigned short* Bql = g_wtl;
    const unsigned short* Bkh = g_wth + (size_t)1*512*512;
    const unsigned short* Bvh = g_wth + (size_t)2*512*512;

    int n0   = blockIdx.x * 64;
    int row0 = blockIdx.y * 128;

    float accq[2][4][4], acck[2][4][4], accv[2][4][4];
    #pragma unroll
    for (int mi = 0; mi < 2; mi++)
        #pragma unroll
        for (int ni = 0; ni < 4; ni++)
            #pragma unroll
            for (int c = 0; c < 4; c++) {
                accq[mi][ni][c] = 0.f;
                acck[mi][ni][c] = 0.f;
                accv[mi][ni][c] = 0.f;
            }

    auto issue_chunk = [&](int kb, uint32_t bufo) {
        int kbase = kb * 64;
        // A: 2 arrays x 1024 uint4 = 2048 / 256 thr = 8 iters
        #pragma unroll
        for (int i = 0; i < 8; i++) {
            int idx = i*256 + tid;
            int a = idx >> 10;
            int rem = idx & 1023;
            int row = rem >> 3, q8 = rem & 7;
            const unsigned short* srcp = a ? g_al : g_ah;
            CP_ASYNC16(sbase + bufo + (a ? QG_AL : QG_AH) + row*144 + q8*16,
                       &srcp[(size_t)(row0+row)*512 + kbase + q8*8]);
        }
        // B: 4 arrays x 512 uint4 = 2048 / 256 = 8 iters
        #pragma unroll
        for (int i = 0; i < 8; i++) {
            int idx = i*256 + tid;
            int a = idx >> 9;                 // 0=BQH 1=BQL 2=BKH 3=BVH
            int rem = idx & 511;
            int row = rem >> 3, q8 = rem & 7;
            const unsigned short* srcp = (a == 0) ? Bqh : (a == 1) ? Bql
                                       : (a == 2) ? Bkh : Bvh;
            int dsto = (a == 0) ? QG_BQH : (a == 1) ? QG_BQL
                     : (a == 2) ? QG_BKH : QG_BVH;
            CP_ASYNC16(sbase + bufo + dsto + row*144 + q8*16,
                       &srcp[(size_t)(n0+row)*512 + kbase + q8*8]);
        }
        CP_COMMIT();
    };

    issue_chunk(0, 0);

    for (int kb = 0; kb < 8; kb++) {
        uint32_t bufo = (kb & 1) ? QG_BUF : 0;
        CP_WAIT0();
        __syncthreads();
        if (kb + 1 < 8)
            issue_chunk(kb + 1, ((kb + 1) & 1) ? QG_BUF : 0);

        #pragma unroll
        for (int ks = 0; ks < 4; ks++) {
            uint32_t a_hi[2][4], a_lo[2][4];
            #pragma unroll
            for (int mi = 0; mi < 2; mi++) {
                int row = wm*32 + mi*16 + (lane & 15);
                int kcol = ks*16 + ((lane >> 4) << 3);
                uint32_t off = bufo + (uint32_t)(row*144 + kcol*2);
                ldsm_x4(a_hi[mi][0], a_hi[mi][1], a_hi[mi][2], a_hi[mi][3],
                        sbase + QG_AH + off);
                ldsm_x4(a_lo[mi][0], a_lo[mi][1], a_lo[mi][2], a_lo[mi][3],
                        sbase + QG_AL + off);
            }
            #pragma unroll
            for (int g = 0; g < 2; g++) {
                int rr = lane & 7;
                int hk = (lane >> 3) & 1;
                int hn = (lane >> 4) & 1;
                int nrow = wn*32 + g*16 + hn*8 + rr;
                int kcol = ks*16 + hk*8;
                uint32_t off = bufo + (uint32_t)(nrow*144 + kcol*2);
                uint32_t bqh[4], bql[4], bkh[4], bvh[4];
                ldsm_x4(bqh[0], bqh[1], bqh[2], bqh[3], sbase + QG_BQH + off);
                ldsm_x4(bql[0], bql[1], bql[2], bql[3], sbase + QG_BQL + off);
                ldsm_x4(bkh[0], bkh[1], bkh[2], bkh[3], sbase + QG_BKH + off);
                ldsm_x4(bvh[0], bvh[1], bvh[2], bvh[3], sbase + QG_BVH + off);
                #pragma unroll
                for (int sub = 0; sub < 2; sub++) {
                    int ni = g*2 + sub;
                    #pragma unroll
                    for (int mi = 0; mi < 2; mi++) {
                        mma_f16(accq[mi][ni], a_hi[mi], &bqh[sub*2]);
                        mma_f16(accq[mi][ni], a_lo[mi], &bqh[sub*2]);
                        mma_f16(accq[mi][ni], a_hi[mi], &bql[sub*2]);
                        mma_f16(acck[mi][ni], a_hi[mi], &bkh[sub*2]);
                        mma_f16(acck[mi][ni], a_lo[mi], &bkh[sub*2]);
                        mma_f16(accv[mi][ni], a_hi[mi], &bvh[sub*2]);
                        mma_f16(accv[mi][ni], a_lo[mi], &bvh[sub*2]);
                    }
                }
            }
        }
    }

    float qscale = 0.125f * LOG2E_F;
    #pragma unroll
    for (int mi = 0; mi < 2; mi++) {
        #pragma unroll
        for (int ni = 0; ni < 4; ni++) {
            int nl = wn*32 + ni*8 + (lane & 3)*2;
            float bq0 = bq[n0 + nl], bq1 = bq[n0 + nl + 1];
            float bk0 = bk[n0 + nl], bk1 = bk[n0 + nl + 1];
            float bv0 = bv[n0 + nl], bv1 = bv[n0 + nl + 1];
            #pragma unroll
            for (int half = 0; half < 2; half++) {
                int m = row0 + wm*32 + mi*16 + (lane >> 2) + half*8;
                int enc = m >> 12, b = (m >> 10) & 3, l = m & 1023;
                int h = n0 >> 6;
                size_t idx = ((((size_t)(enc*B_ + b))*H_ + h)*L_ + l)*HD_ + nl;
                float qx = (accq[mi][ni][half*2+0] + bq0) * qscale;
                float qy = (accq[mi][ni][half*2+1] + bq1) * qscale;
                uint32_t hi, lo; split2(qx, qy, hi, lo);
                *(uint32_t*)&g_qh[idx] = hi;
                *(uint32_t*)&g_ql[idx] = lo;
                *(uint32_t*)&g_kh[idx] = pack2h(acck[mi][ni][half*2+0] + bk0,
                                                acck[mi][ni][half*2+1] + bk1);
                *(uint32_t*)&g_vh[idx] = pack2h(accv[mi][ni][half*2+0] + bv0,
                                                accv[mi][ni][half*2+1] + bv1);
            }
        }
    }
}

// ===========================================================================
// Out-proj GEMM: ctx (hi/lo) x wo (hi), 2-term, fp32 out. 128M x 64N.
// ===========================================================================
#define GM_BUF  46080
#define GM_AH   0
#define GM_AL   18432
#define GM_BH   36864
#define GM_SMEM 92160

__global__ __launch_bounds__(256) void oproj_mma_kernel(
    const float* __restrict__ bo, float* __restrict__ outp)
{
    extern __shared__ __align__(16) unsigned char smem[];
    uint32_t sbase = smem_u32(smem);

    int tid = threadIdx.x;
    int wid = tid >> 5, lane = tid & 31;
    int wm = wid & 3, wn = wid >> 2;

    const unsigned short* Bh = g_wth + (size_t)3*512*512;
    int n0   = blockIdx.x * 64;
    int row0 = blockIdx.y * 128;

    float acc[2][4][4];
    #pragma unroll
    for (int mi = 0; mi < 2; mi++)
        #pragma unroll
        for (int ni = 0; ni < 4; ni++)
            #pragma unroll
            for (int c = 0; c < 4; c++) acc[mi][ni][c] = 0.f;

    auto issue_chunk = [&](int kb, uint32_t bufo) {
        int kbase = kb * 64;
        #pragma unroll
        for (int i = 0; i < 8; i++) {
            int idx = i*256 + tid;
            int a = idx >> 10;
            int rem = idx & 1023;
            int row = rem >> 3, q8 = rem & 7;
            const unsigned short* srcp = a ? g_cl : g_ch;
            CP_ASYNC16(sbase + bufo + (a ? GM_AL : GM_AH) + row*144 + q8*16,
                       &srcp[(size_t)(row0+row)*512 + kbase + q8*8]);
        }
        #pragma unroll
        for (int i = 0; i < 2; i++) {
            int idx = i*256 + tid;
            int row = idx >> 3, q8 = idx & 7;
            CP_ASYNC16(sbase + bufo + GM_BH + row*144 + q8*16,
                       &Bh[(size_t)(n0+row)*512 + kbase + q8*8]);
        }
        CP_COMMIT();
    };

    issue_chunk(0, 0);

    for (int kb = 0; kb < 8; kb++) {
        uint32_t bufo = (kb & 1) ? GM_BUF : 0;
        CP_WAIT0();
        __syncthreads();
        if (kb + 1 < 8)
            issue_chunk(kb + 1, ((kb + 1) & 1) ? GM_BUF : 0);

        #pragma unroll
        for (int ks = 0; ks < 4; ks++) {
            uint32_t a_hi[2][4], a_lo[2][4], b_hi[8];
            #pragma unroll
            for (int mi = 0; mi < 2; mi++) {
                int row = wm*32 + mi*16 + (lane & 15);
                int kcol = ks*16 + ((lane >> 4) << 3);
                uint32_t off = bufo + (uint32_t)(row*144 + kcol*2);
                ldsm_x4(a_hi[mi][0], a_hi[mi][1], a_hi[mi][2], a_hi[mi][3],
                        sbase + GM_AH + off);
                ldsm_x4(a_lo[mi][0], a_lo[mi][1], a_lo[mi][2], a_lo[mi][3],
                        sbase + GM_AL + off);
            }
            #pragma unroll
            for (int g = 0; g < 2; g++) {
                int rr = lane & 7;
                int hk = (lane >> 3) & 1;
                int hn = (lane >> 4) & 1;
                int nrow = wn*32 + g*16 + hn*8 + rr;
                int kcol = ks*16 + hk*8;
                uint32_t off = bufo + (uint32_t)(nrow*144 + kcol*2);
                ldsm_x4(b_hi[g*4+0], b_hi[g*4+1], b_hi[g*4+2], b_hi[g*4+3],
                        sbase + GM_BH + off);
            }
            #pragma unroll
            for (int mi = 0; mi < 2; mi++)
                #pragma unroll
                for (int ni = 0; ni < 4; ni++) {
                    mma_f16(acc[mi][ni], a_hi[mi], &b_hi[ni*2]);
                    mma_f16(acc[mi][ni], a_lo[mi], &b_hi[ni*2]);
                }
        }
    }

    #pragma unroll
    for (int mi = 0; mi < 2; mi++) {
        #pragma unroll
        for (int ni = 0; ni < 4; ni++) {
            int nl = wn*32 + ni*8 + (lane & 3)*2;
            float b0 = bo[n0 + nl], b1 = bo[n0 + nl + 1];
            #pragma unroll
            for (int half = 0; half < 2; half++) {
                int m = row0 + wm*32 + mi*16 + (lane >> 2) + half*8;
                float2 o;
                o.x = acc[mi][ni][half*2+0] + b0;
                o.y = acc[mi][ni][half*2+1] + b1;
                *(float2*)&outp[(size_t)m*D_ + n0 + nl] = o;
            }
        }
    }
}

// ===========================================================================
// Flash attention (R13 config, best known): 32 q-rows/warp, 128/CTA, 4 warps,
// Q-hi frags resident, Q-lo reloaded per ks. No min-blocks cap.
// ===========================================================================
#define AT_BUF  18432
#define AT_KH   0
#define AT_VH   9216
#define AT_Q    36864
#define AT_QL   (36864 + 18432)
#define AT_SMEM 73728

__global__ __launch_bounds__(128) void attn_mma_kernel()
{
    extern __shared__ __align__(16) unsigned char smem[];
    uint32_t sbase = smem_u32(smem);

    int tid = threadIdx.x;
    int wid = tid >> 5, lane = tid & 31;
    int r = lane >> 2, cq = lane & 3;

    int qt = blockIdx.x, bh = blockIdx.y, dir = blockIdx.z;
    int b = bh >> 3, h = bh & 7;
    int enc_q = dir, enc_kv = 1 - dir;

    size_t qoff  = ((size_t)((enc_q *B_ + b)*H_ + h))*L_*HD_;
    size_t kvoff = ((size_t)((enc_kv*B_ + b)*H_ + h))*L_*HD_;
    const unsigned short* Qh = g_qh + qoff;
    const unsigned short* Ql = g_ql + qoff;
    const unsigned short* Kh = g_kh + kvoff;
    const unsigned short* Vh = g_vh + kvoff;
    const unsigned short* mb = g_mb + ((size_t)dir*B_ + b)*L_*L_;
    int q0 = qt * 128;

    #pragma unroll
    for (int i = 0; i < 16; i++) {
        int idx = i*128 + tid;
        int a = idx >> 10;
        int rem = idx & 1023;
        int row = rem >> 3, q8 = rem & 7;
        const unsigned short* srcp = a ? Ql : Qh;
        CP_ASYNC16(sbase + (a ? AT_QL : AT_Q) + row*144 + q8*16,
                   &srcp[(size_t)(q0+row)*HD_ + q8*8]);
    }
    CP_COMMIT();
    CP_WAIT0();
    __syncthreads();

    auto issue_kv = [&](int t, uint32_t bufo) {
        int k0 = t * 64;
        #pragma unroll
        for (int i = 0; i < 8; i++) {
            int idx = i*128 + tid;
            int a = idx >> 9;
            int rem = idx & 511;
            int row = rem >> 3, q8 = rem & 7;
            const unsigned short* srcp = a ? Vh : Kh;
            int dsto = a ? AT_VH : AT_KH;
            CP_ASYNC16(sbase + bufo + dsto + row*144 + q8*16,
                       &srcp[(size_t)(k0+row)*HD_ + q8*8]);
        }
        CP_COMMIT();
    };

    issue_kv(0, 0);

    uint32_t aq_h[2][4][4];
    #pragma unroll
    for (int mt = 0; mt < 2; mt++) {
        #pragma unroll
        for (int ks = 0; ks < 4; ks++) {
            int row = wid*32 + mt*16 + (lane & 15);
            int kcol = ks*16 + ((lane >> 4) << 3);
            uint32_t off = (uint32_t)(row*144 + kcol*2);
            ldsm_x4(aq_h[mt][ks][0], aq_h[mt][ks][1],
                    aq_h[mt][ks][2], aq_h[mt][ks][3], sbase + AT_Q + off);
        }
    }

    float o_acc[2][8][4];
    #pragma unroll
    for (int mt = 0; mt < 2; mt++)
        #pragma unroll
        for (int nt = 0; nt < 8; nt++)
            #pragma unroll
            for (int c = 0; c < 4; c++) o_acc[mt][nt][c] = 0.f;
    float mreg[2][2], lreg[2][2];
    #pragma unroll
    for (int mt = 0; mt < 2; mt++) {
        mreg[mt][0] = -3.0e38f; mreg[mt][1] = -3.0e38f;
        lreg[mt][0] = 0.f;      lreg[mt][1] = 0.f;
    }

    int qgw = q0 + wid*32 + r;
    const unsigned short* mbrow[2][2];
    #pragma unroll
    for (int mt = 0; mt < 2; mt++) {
        mbrow[mt][0] = mb + (size_t)(qgw + mt*16)*L_ + cq*2;
        mbrow[mt][1] = mb + (size_t)(qgw + mt*16 + 8)*L_ + cq*2;
    }

    for (int t = 0; t < 16; t++) {
        int k0 = t * 64;
        uint32_t bufo = (t & 1) ? AT_BUF : 0;
        CP_WAIT0();
        __syncthreads();
        if (t + 1 < 16)
            issue_kv(t + 1, ((t + 1) & 1) ? AT_BUF : 0);

        float s_acc[2][8][4];
        #pragma unroll
        for (int mt = 0; mt < 2; mt++)
            #pragma unroll
            for (int nt = 0; nt < 8; nt++)
                #pragma unroll
                for (int c = 0; c < 4; c++) s_acc[mt][nt][c] = 0.f;

        #pragma unroll
        for (int ks = 0; ks < 4; ks++) {
            uint32_t aq_l[2][4];
            #pragma unroll
            for (int mt = 0; mt < 2; mt++) {
                int row = wid*32 + mt*16 + (lane & 15);
                int kcol = ks*16 + ((lane >> 4) << 3);
                ldsm_x4(aq_l[mt][0], aq_l[mt][1], aq_l[mt][2], aq_l[mt][3],
                        sbase + AT_QL + (uint32_t)(row*144 + kcol*2));
            }
            #pragma unroll
            for (int g = 0; g < 4; g++) {
                uint32_t bk[4];
                int rr = lane & 7;
                int hk = (lane >> 3) & 1;
                int hn = (lane >> 4) & 1;
                int nrow = g*16 + hn*8 + rr;
                int kcol = ks*16 + hk*8;
                uint32_t off = bufo + (uint32_t)(nrow*144 + kcol*2);
                ldsm_x4(bk[0], bk[1], bk[2], bk[3], sbase + AT_KH + off);
                int n0t = g*2, n1t = g*2 + 1;
                #pragma unroll
                for (int mt = 0; mt < 2; mt++) {
                    mma_f16(s_acc[mt][n0t], aq_h[mt][ks], &bk[0]);
                    mma_f16(s_acc[mt][n1t], aq_h[mt][ks], &bk[2]);
                    mma_f16(s_acc[mt][n0t], aq_l[mt], &bk[0]);
                    mma_f16(s_acc[mt][n1t], aq_l[mt], &bk[2]);
                }
            }
        }

        #pragma unroll
        for (int mt = 0; mt < 2; mt++) {
            #pragma unroll
            for (int nt = 0; nt < 8; nt++) {
                int cc = k0 + nt*8;
                float2 b0v = h2unpack(*(const uint32_t*)&mbrow[mt][0][cc]);
                float2 b1v = h2unpack(*(const uint32_t*)&mbrow[mt][1][cc]);
                s_acc[mt][nt][0] += b0v.x;
                s_acc[mt][nt][1] += b0v.y;
                s_acc[mt][nt][2] += b1v.x;
                s_acc[mt][nt][3] += b1v.y;
            }

            float mx0 = -3.0e38f, mx1 = -3.0e38f;
            #pragma unroll
            for (int nt = 0; nt < 8; nt++) {
                mx0 = fmaxf(mx0, fmaxf(s_acc[mt][nt][0], s_acc[mt][nt][1]));
                mx1 = fmaxf(mx1, fmaxf(s_acc[mt][nt][2], s_acc[mt][nt][3]));
            }
            mx0 = fmaxf(mx0, __shfl_xor_sync(0xffffffffu, mx0, 1));
            mx0 = fmaxf(mx0, __shfl_xor_sync(0xffffffffu, mx0, 2));
            mx1 = fmaxf(mx1, __shfl_xor_sync(0xffffffffu, mx1, 1));
            mx1 = fmaxf(mx1, __shfl_xor_sync(0xffffffffu, mx1, 2));

            float mn0 = fmaxf(mreg[mt][0], mx0);
            float mn1 = fmaxf(mreg[mt][1], mx1);
            float c0 = ex2f(mreg[mt][0] - mn0);
            float c1 = ex2f(mreg[mt][1] - mn1);
            mreg[mt][0] = mn0; mreg[mt][1] = mn1;

            float rs0 = 0.f, rs1 = 0.f;
            #pragma unroll
            for (int nt = 0; nt < 8; nt++) {
                s_acc[mt][nt][0] = ex2f(s_acc[mt][nt][0] - mn0); rs0 += s_acc[mt][nt][0];
                s_acc[mt][nt][1] = ex2f(s_acc[mt][nt][1] - mn0); rs0 += s_acc[mt][nt][1];
                s_acc[mt][nt][2] = ex2f(s_acc[mt][nt][2] - mn1); rs1 += s_acc[mt][nt][2];
                s_acc[mt][nt][3] = ex2f(s_acc[mt][nt][3] - mn1); rs1 += s_acc[mt][nt][3];
            }
            rs0 += __shfl_xor_sync(0xffffffffu, rs0, 1);
            rs0 += __shfl_xor_sync(0xffffffffu, rs0, 2);
            rs1 += __shfl_xor_sync(0xffffffffu, rs1, 1);
            rs1 += __shfl_xor_sync(0xffffffffu, rs1, 2);
            lreg[mt][0] = lreg[mt][0]*c0 + rs0;
            lreg[mt][1] = lreg[mt][1]*c1 + rs1;

            #pragma unroll
            for (int nt = 0; nt < 8; nt++) {
                o_acc[mt][nt][0] *= c0; o_acc[mt][nt][1] *= c0;
                o_acc[mt][nt][2] *= c1; o_acc[mt][nt][3] *= c1;
            }
        }

        #pragma unroll
        for (int ks = 0; ks < 4; ks++) {
            int t0 = 2*ks, t1 = 2*ks + 1;
            uint32_t ap[2][4];
            #pragma unroll
            for (int mt = 0; mt < 2; mt++) {
                ap[mt][0] = pack2h(s_acc[mt][t0][0], s_acc[mt][t0][1]);
                ap[mt][1] = pack2h(s_acc[mt][t0][2], s_acc[mt][t0][3]);
                ap[mt][2] = pack2h(s_acc[mt][t1][0], s_acc[mt][t1][1]);
                ap[mt][3] = pack2h(s_acc[mt][t1][2], s_acc[mt][t1][3]);
            }
            #pragma unroll
            for (int g = 0; g < 4; g++) {
                uint32_t bv[4];
                int kk  = ks*16 + ((lane >> 3) & 1)*8 + (lane & 7);
                int hdo = g*16 + ((lane >> 4) & 1)*8;
                uint32_t off = bufo + (uint32_t)(kk*144 + hdo*2);
                ldsm_x4_t(bv[0], bv[1], bv[2], bv[3], sbase + AT_VH + off);
                int n0t = g*2, n1t = g*2 + 1;
                #pragma unroll
                for (int mt = 0; mt < 2; mt++) {
                    mma_f16(o_acc[mt][n0t], ap[mt], &bv[0]);
                    mma_f16(o_acc[mt][n1t], ap[mt], &bv[2]);
                }
            }
        }
    }

    #pragma unroll
    for (int mt = 0; mt < 2; mt++) {
        float inv0 = 1.f / lreg[mt][0];
        float inv1 = 1.f / lreg[mt][1];
        int row0g = qgw + mt*16;
        size_t base0 = ((size_t)(enc_q*B_ + b)*L_ + row0g)*D_ + h*64 + cq*2;
        size_t base1 = ((size_t)(enc_q*B_ + b)*L_ + row0g + 8)*D_ + h*64 + cq*2;
        #pragma unroll
        for (int nt = 0; nt < 8; nt++) {
            uint32_t hi0, lo0, hi1, lo1;
            split2(o_acc[mt][nt][0]*inv0, o_acc[mt][nt][1]*inv0, hi0, lo0);
            split2(o_acc[mt][nt][2]*inv1, o_acc[mt][nt][3]*inv1, hi1, lo1);
            *(uint32_t*)&g_ch[base0 + nt*8] = hi0;
            *(uint32_t*)&g_cl[base0 + nt*8] = lo0;
            *(uint32_t*)&g_ch[base1 + nt*8] = hi1;
            *(uint32_t*)&g_cl[base1 + nt*8] = lo1;
        }
    }
}

// ---------------------------------------------------------------------------
extern "C" void kernel_launch(void* const* d_in, const int* in_sizes, int n_in,
                              void* d_out, int out_size)
{
    const float* u_enc     = (const float*)d_in[0];
    const float* e_enc     = (const float*)d_in[1];
    const float* logit_bpp = (const float*)d_in[2];
    const void*  ue_mask   = d_in[3];
    const void*  eu_mask   = d_in[4];
    const float* wq_k = (const float*)d_in[5];
    const float* wq_b = (const float*)d_in[6];
    const float* wk_k = (const float*)d_in[7];
    const float* wk_b = (const float*)d_in[8];
    const float* wv_k = (const float*)d_in[9];
    const float* wv_b = (const float*)d_in[10];
    const float* wo_k = (const float*)d_in[11];
    const float* wo_b = (const float*)d_in[12];
    const float* bpp_w = (const float*)d_in[13];
    const float* bpp_b = (const float*)d_in[14];
    float* out = (float*)d_out;

    cudaFuncSetAttribute((const void*)attn_mma_kernel,
                         cudaFuncAttributeMaxDynamicSharedMemorySize, AT_SMEM);
    cudaFuncSetAttribute((const void*)qkv_mma_kernel,
                         cudaFuncAttributeMaxDynamicSharedMemorySize, QG_SMEM);
    cudaFuncSetAttribute((const void*)oproj_mma_kernel,
                         cudaFuncAttributeMaxDynamicSharedMemorySize, GM_SMEM);

    // 0) mask dtype detection
    mask_detect_kernel<<<1, 256>>>((const unsigned int*)ue_mask);
    // 1) fused prep
    prep_kernel<<<5120, 256>>>(logit_bpp, bpp_w, bpp_b, ue_mask, eu_mask,
                               u_enc, e_enc, wq_k, wk_k, wv_k, wo_k);
    // 2) fused QKV projection (single kernel, shared A tiles)
    qkv_mma_kernel<<<dim3(8, 64), 256, QG_SMEM>>>(wq_b, wk_b, wv_b);
    // 3) fused attention (R13 best config)
    attn_mma_kernel<<<dim3(8, 32, 2), 128, AT_SMEM>>>();
    // 4) output projection -> d_out
    oproj_mma_kernel<<<dim3(8, 64), 256, GM_SMEM>>>(wo_b, out);
}

// round 16
// speedup vs baseline: 1.1808x; 1.0165x over previous
#include <cuda_runtime.h>
#include <cuda_fp16.h>
#include <math.h>
#include <float.h>
#include <stdint.h>
#include <string.h>

#define B_  4
#define L_  1024
#define D_  512
#define H_  8
#define HD_ 64
#define PROJ_ELEMS (2*B_*H_*L_*HD_)   /* 4,194,304 */
#define MASK_ELEMS ((size_t)B_*L_*L_) /* 4,194,304 */
#define ENC_ELEMS  (8192*512)
#define LOG2E_F 1.4426950408889634f

// producer-split fp16 storage
__device__ unsigned short g_ah[ENC_ELEMS], g_al[ENC_ELEMS];      // [u;e] inputs
__device__ unsigned short g_wth[4*512*512], g_wtl[4*512*512];    // W^T, n-major
__device__ unsigned short g_qh[PROJ_ELEMS], g_ql[PROJ_ELEMS];    // Q hi/lo
__device__ unsigned short g_kh[PROJ_ELEMS];                      // K single fp16
__device__ unsigned short g_vh[PROJ_ELEMS];                      // V single fp16
__device__ unsigned short g_ch[PROJ_ELEMS], g_cl[PROJ_ELEMS];    // ctx hi/lo
__device__ unsigned short g_mb[2*B_*L_*L_];  // fp16 (bias*log2e) | -30000 masked
__device__ int g_mtype;

// ===========================================================================
// helpers
// ===========================================================================
__device__ __forceinline__ uint32_t smem_u32(const void* p) {
    uint32_t a;
    asm("{ .reg .u64 t; cvta.to.shared.u64 t, %1; cvt.u32.u64 %0, t; }"
        : "=r"(a) : "l"(p));
    return a;
}
#define CP_ASYNC16(saddr, gptr) \
    asm volatile("cp.async.ca.shared.global [%0], [%1], 16;" \
                 :: "r"(saddr), "l"(gptr))
#define CP_COMMIT() asm volatile("cp.async.commit_group;" ::: "memory")
#define CP_WAIT0()  asm volatile("cp.async.wait_group 0;" ::: "memory")

__device__ __forceinline__ float ex2f(float x) {
    float r;
    asm("ex2.approx.f32 %0, %1;" : "=f"(r) : "f"(x));
    return r;
}
__device__ __forceinline__ void ldsm_x4(uint32_t& r0, uint32_t& r1,
                                        uint32_t& r2, uint32_t& r3,
                                        uint32_t addr) {
    asm volatile("ldmatrix.sync.aligned.m8n8.x4.shared.b16 {%0,%1,%2,%3}, [%4];"
                 : "=r"(r0), "=r"(r1), "=r"(r2), "=r"(r3) : "r"(addr));
}
__device__ __forceinline__ void ldsm_x4_t(uint32_t& r0, uint32_t& r1,
                                          uint32_t& r2, uint32_t& r3,
                                          uint32_t addr) {
    asm volatile("ldmatrix.sync.aligned.m8n8.x4.trans.shared.b16 {%0,%1,%2,%3}, [%4];"
                 : "=r"(r0), "=r"(r1), "=r"(r2), "=r"(r3) : "r"(addr));
}
__device__ __forceinline__ void mma_f16(float* c, const uint32_t* a,
                                        const uint32_t* b) {
    asm volatile("mma.sync.aligned.m16n8k16.row.col.f32.f16.f16.f32 "
                 "{%0,%1,%2,%3}, {%4,%5,%6,%7}, {%8,%9}, {%0,%1,%2,%3};"
                 : "+f"(c[0]), "+f"(c[1]), "+f"(c[2]), "+f"(c[3])
                 : "r"(a[0]), "r"(a[1]), "r"(a[2]), "r"(a[3]),
                   "r"(b[0]), "r"(b[1]));
}
__device__ __forceinline__ unsigned short f2h_bits(float x) {
    __half h = __float2half_rn(x);
    unsigned short u; memcpy(&u, &h, 2); return u;
}
__device__ __forceinline__ float hbits2f(unsigned short u) {
    __half h; memcpy(&h, &u, 2); return __half2float(h);
}
__device__ __forceinline__ void split2(float x, float y, uint32_t& hi, uint32_t& lo) {
    unsigned short hx = f2h_bits(x), hy = f2h_bits(y);
    unsigned short lx = f2h_bits(x - hbits2f(hx));
    unsigned short ly = f2h_bits(y - hbits2f(hy));
    hi = (uint32_t)hx | ((uint32_t)hy << 16);
    lo = (uint32_t)lx | ((uint32_t)ly << 16);
}
__device__ __forceinline__ uint32_t pack2h(float x, float y) {
    return (uint32_t)f2h_bits(x) | ((uint32_t)f2h_bits(y) << 16);
}
__device__ __forceinline__ float2 h2unpack(uint32_t w) {
    __half2 h; memcpy(&h, &w, 4);
    return __half22float2(h);
}

// ===========================================================================
// Mask dtype detection
// ===========================================================================
__global__ void mask_detect_kernel(const unsigned int* __restrict__ m)
{
    __shared__ int viol[3];
    if (threadIdx.x < 3) viol[threadIdx.x] = 0;
    __syncthreads();
    int v0 = 0, v1 = 0, v2 = 0;
    for (int i = threadIdx.x; i < 16384; i += 256) {
        unsigned w = m[i];
        if (w > 1u) v0 = 1;
        if (w != 0u && w != 0x3F800000u) v1 = 1;
        if (w != 0u && w != 0x3F800000u && w != 0x00003F80u && w != 0x3F803F80u) v2 = 1;
    }
    if (v0) atomicOr(&viol[0], 1);
    if (v1) atomicOr(&viol[1], 1);
    if (v2) atomicOr(&viol[2], 1);
    __syncthreads();
    if (threadIdx.x == 0) {
        int t;
        if      (!viol[0]) t = 1;
        else if (!viol[1]) t = 2;
        else if (!viol[2]) t = 3;
        else               t = 0;
        g_mtype = t;
    }
}

// ===========================================================================
// Fused prep: blocks [0,2048) maskbias, [2048,4096) enc split, [4096,5120) wt.
// ===========================================================================
__global__ __launch_bounds__(256) void prep_kernel(
    const float* __restrict__ lb,
    const float* __restrict__ wp, const float* __restrict__ bp,
    const void* __restrict__ ue, const void* __restrict__ eu,
    const float* __restrict__ u, const float* __restrict__ e,
    const float* __restrict__ wq, const float* __restrict__ wk,
    const float* __restrict__ wv, const float* __restrict__ wo)
{
    __shared__ float s[32][33];
    int bx = blockIdx.x;
    int tid = threadIdx.x;
    int tx = tid & 31, ty = tid >> 5;

    if (bx < 2048) {
        int dir = bx >> 10;
        int q0 = ((bx >> 5) & 31) * 32;
        int k0 = (bx & 31) * 32;
        int mt = g_mtype;
        float w = wp[0] * LOG2E_F, bb = bp[0] * LOG2E_F;
        const void* msk = dir ? eu : ue;
        unsigned short* dst = g_mb + (size_t)dir * MASK_ELEMS;

        if (dir == 1) {
            #pragma unroll
            for (int i = ty; i < 32; i += 8)
                s[i][tx] = lb[(size_t)(k0+i)*L_ + q0 + tx];
            __syncthreads();
        }
        unsigned short mk = f2h_bits(-30000.0f);
        #pragma unroll
        for (int i = ty; i < 32; i += 8) {
            float bias;
            if (dir == 0) bias = fmaf(w, lb[(size_t)(q0+i)*L_ + k0 + tx], bb);
            else          bias = fmaf(w, s[tx][i], bb);
            unsigned short bh = f2h_bits(bias);
            size_t rowoff = (size_t)(q0+i)*L_ + k0 + tx;
            #pragma unroll
            for (int b = 0; b < B_; b++) {
                size_t idx = ((size_t)b << 20) + rowoff;
                bool mv;
                if      (mt == 1) mv = ((const int*)msk)[idx] != 0;
                else if (mt == 2) mv = ((const float*)msk)[idx] != 0.f;
                else if (mt == 3) mv = ((const unsigned short*)msk)[idx] != 0;
                else              mv = ((const unsigned char*)msk)[idx] != 0;
                dst[idx] = mv ? bh : mk;
            }
        }
    } else if (bx < 4096) {
        int idx = bx - 2048;
        int z = idx >> 10, blk = idx & 1023;
        const float* src = z ? e : u;
        size_t base4 = (size_t)z * (4096*512/4);
        size_t stride = 1024u * 256u;
        for (size_t i4 = (size_t)blk*256 + tid; i4 < 4096*512/4; i4 += stride) {
            float4 v = ((const float4*)src)[i4];
            uint32_t h01, l01, h23, l23;
            split2(v.x, v.y, h01, l01);
            split2(v.z, v.w, h23, l23);
            ((uint2*)g_ah)[base4 + i4] = make_uint2(h01, h23);
            ((uint2*)g_al)[base4 + i4] = make_uint2(l01, l23);
        }
    } else {
        int idx = bx - 4096;
        int z = idx >> 8, by = (idx >> 4) & 15, bxx = idx & 15;
        const float* src = (z == 0) ? wq : (z == 1) ? wk : (z == 2) ? wv : wo;
        int x  = bxx*32 + tx;
        int y0 = by*32;
        #pragma unroll
        for (int i = ty; i < 32; i += 8)
            s[i][tx] = src[(size_t)(y0+i)*512 + x];
        __syncthreads();
        size_t base = (size_t)z * 512*512;
        int ko = y0 + tx;
        #pragma unroll
        for (int i = ty; i < 32; i += 8) {
            float v = s[tx][i];
            unsigned short h = f2h_bits(v);
            unsigned short l = f2h_bits(v - hbits2f(h));
            size_t widx = base + (size_t)(bxx*32+i)*512 + ko;
            g_wth[widx] = h;
            g_wtl[widx] = l;
        }
    }
}

// ===========================================================================
// Fused QKV GEMM (unchanged from R15)
// ===========================================================================
#define QG_BUF  73728
#define QG_AH   0
#define QG_AL   18432
#define QG_BQH  36864
#define QG_BQL  46080
#define QG_BKH  55296
#define QG_BVH  64512
#define QG_SMEM 147456

__global__ __launch_bounds__(256) void qkv_mma_kernel(
    const float* __restrict__ bq, const float* __restrict__ bk,
    const float* __restrict__ bv)
{
    extern __shared__ __align__(16) unsigned char smem[];
    uint32_t sbase = smem_u32(smem);

    int tid = threadIdx.x;
    int wid = tid >> 5, lane = tid & 31;
    int wm = wid & 3, wn = wid >> 2;

    const unsigned short* Bqh = g_wth;
    const unsigned short* Bql = g_wtl;
    const unsigned short* Bkh = g_wth + (size_t)1*512*512;
    const unsigned short* Bvh = g_wth + (size_t)2*512*512;

    int n0   = blockIdx.x * 64;
    int row0 = blockIdx.y * 128;

    float accq[2][4][4], acck[2][4][4], accv[2][4][4];
    #pragma unroll
    for (int mi = 0; mi < 2; mi++)
        #pragma unroll
        for (int ni = 0; ni < 4; ni++)
            #pragma unroll
            for (int c = 0; c < 4; c++) {
                accq[mi][ni][c] = 0.f;
                acck[mi][ni][c] = 0.f;
                accv[mi][ni][c] = 0.f;
            }

    auto issue_chunk = [&](int kb, uint32_t bufo) {
        int kbase = kb * 64;
        #pragma unroll
        for (int i = 0; i < 8; i++) {
            int idx = i*256 + tid;
            int a = idx >> 10;
            int rem = idx & 1023;
            int row = rem >> 3, q8 = rem & 7;
            const unsigned short* srcp = a ? g_al : g_ah;
            CP_ASYNC16(sbase + bufo + (a ? QG_AL : QG_AH) + row*144 + q8*16,
                       &srcp[(size_t)(row0+row)*512 + kbase + q8*8]);
        }
        #pragma unroll
        for (int i = 0; i < 8; i++) {
            int idx = i*256 + tid;
            int a = idx >> 9;
            int rem = idx & 511;
            int row = rem >> 3, q8 = rem & 7;
            const unsigned short* srcp = (a == 0) ? Bqh : (a == 1) ? Bql
                                       : (a == 2) ? Bkh : Bvh;
            int dsto = (a == 0) ? QG_BQH : (a == 1) ? QG_BQL
                     : (a == 2) ? QG_BKH : QG_BVH;
            CP_ASYNC16(sbase + bufo + dsto + row*144 + q8*16,
                       &srcp[(size_t)(n0+row)*512 + kbase + q8*8]);
        }
        CP_COMMIT();
    };

    issue_chunk(0, 0);

    for (int kb = 0; kb < 8; kb++) {
        uint32_t bufo = (kb & 1) ? QG_BUF : 0;
        CP_WAIT0();
        __syncthreads();
        if (kb + 1 < 8)
            issue_chunk(kb + 1, ((kb + 1) & 1) ? QG_BUF : 0);

        #pragma unroll
        for (int ks = 0; ks < 4; ks++) {
            uint32_t a_hi[2][4], a_lo[2][4];
            #pragma unroll
            for (int mi = 0; mi < 2; mi++) {
                int row = wm*32 + mi*16 + (lane & 15);
                int kcol = ks*16 + ((lane >> 4) << 3);
                uint32_t off = bufo + (uint32_t)(row*144 + kcol*2);
                ldsm_x4(a_hi[mi][0], a_hi[mi][1], a_hi[mi][2], a_hi[mi][3],
                        sbase + QG_AH + off);
                ldsm_x4(a_lo[mi][0], a_lo[mi][1], a_lo[mi][2], a_lo[mi][3],
                        sbase + QG_AL + off);
            }
            #pragma unroll
            for (int g = 0; g < 2; g++) {
                int rr = lane & 7;
                int hk = (lane >> 3) & 1;
                int hn = (lane >> 4) & 1;
                int nrow = wn*32 + g*16 + hn*8 + rr;
                int kcol = ks*16 + hk*8;
                uint32_t off = bufo + (uint32_t)(nrow*144 + kcol*2);
                uint32_t bqh[4], bql[4], bkh[4], bvh[4];
                ldsm_x4(bqh[0], bqh[1], bqh[2], bqh[3], sbase + QG_BQH + off);
                ldsm_x4(bql[0], bql[1], bql[2], bql[3], sbase + QG_BQL + off);
                ldsm_x4(bkh[0], bkh[1], bkh[2], bkh[3], sbase + QG_BKH + off);
                ldsm_x4(bvh[0], bvh[1], bvh[2], bvh[3], sbase + QG_BVH + off);
                #pragma unroll
                for (int sub = 0; sub < 2; sub++) {
                    int ni = g*2 + sub;
                    #pragma unroll
                    for (int mi = 0; mi < 2; mi++) {
                        mma_f16(accq[mi][ni], a_hi[mi], &bqh[sub*2]);
                        mma_f16(accq[mi][ni], a_lo[mi], &bqh[sub*2]);
                        mma_f16(accq[mi][ni], a_hi[mi], &bql[sub*2]);
                        mma_f16(acck[mi][ni], a_hi[mi], &bkh[sub*2]);
                        mma_f16(acck[mi][ni], a_lo[mi], &bkh[sub*2]);
                        mma_f16(accv[mi][ni], a_hi[mi], &bvh[sub*2]);
                        mma_f16(accv[mi][ni], a_lo[mi], &bvh[sub*2]);
                    }
                }
            }
        }
    }

    float qscale = 0.125f * LOG2E_F;
    #pragma unroll
    for (int mi = 0; mi < 2; mi++) {
        #pragma unroll
        for (int ni = 0; ni < 4; ni++) {
            int nl = wn*32 + ni*8 + (lane & 3)*2;
            float bq0 = bq[n0 + nl], bq1 = bq[n0 + nl + 1];
            float bk0 = bk[n0 + nl], bk1 = bk[n0 + nl + 1];
            float bv0 = bv[n0 + nl], bv1 = bv[n0 + nl + 1];
            #pragma unroll
            for (int half = 0; half < 2; half++) {
                int m = row0 + wm*32 + mi*16 + (lane >> 2) + half*8;
                int enc = m >> 12, b = (m >> 10) & 3, l = m & 1023;
                int h = n0 >> 6;
                size_t idx = ((((size_t)(enc*B_ + b))*H_ + h)*L_ + l)*HD_ + nl;
                float qx = (accq[mi][ni][half*2+0] + bq0) * qscale;
                float qy = (accq[mi][ni][half*2+1] + bq1) * qscale;
                uint32_t hi, lo; split2(qx, qy, hi, lo);
                *(uint32_t*)&g_qh[idx] = hi;
                *(uint32_t*)&g_ql[idx] = lo;
                *(uint32_t*)&g_kh[idx] = pack2h(acck[mi][ni][half*2+0] + bk0,
                                                acck[mi][ni][half*2+1] + bk1);
                *(uint32_t*)&g_vh[idx] = pack2h(accv[mi][ni][half*2+0] + bv0,
                                                accv[mi][ni][half*2+1] + bv1);
            }
        }
    }
}

// ===========================================================================
// Out-proj GEMM (unchanged from R15)
// ===========================================================================
#define GM_BUF  46080
#define GM_AH   0
#define GM_AL   18432
#define GM_BH   36864
#define GM_SMEM 92160

__global__ __launch_bounds__(256) void oproj_mma_kernel(
    const float* __restrict__ bo, float* __restrict__ outp)
{
    extern __shared__ __align__(16) unsigned char smem[];
    uint32_t sbase = smem_u32(smem);

    int tid = threadIdx.x;
    int wid = tid >> 5, lane = tid & 31;
    int wm = wid & 3, wn = wid >> 2;

    const unsigned short* Bh = g_wth + (size_t)3*512*512;
    int n0   = blockIdx.x * 64;
    int row0 = blockIdx.y * 128;

    float acc[2][4][4];
    #pragma unroll
    for (int mi = 0; mi < 2; mi++)
        #pragma unroll
        for (int ni = 0; ni < 4; ni++)
            #pragma unroll
            for (int c = 0; c < 4; c++) acc[mi][ni][c] = 0.f;

    auto issue_chunk = [&](int kb, uint32_t bufo) {
        int kbase = kb * 64;
        #pragma unroll
        for (int i = 0; i < 8; i++) {
            int idx = i*256 + tid;
            int a = idx >> 10;
            int rem = idx & 1023;
            int row = rem >> 3, q8 = rem & 7;
            const unsigned short* srcp = a ? g_cl : g_ch;
            CP_ASYNC16(sbase + bufo + (a ? GM_AL : GM_AH) + row*144 + q8*16,
                       &srcp[(size_t)(row0+row)*512 + kbase + q8*8]);
        }
        #pragma unroll
        for (int i = 0; i < 2; i++) {
            int idx = i*256 + tid;
            int row = idx >> 3, q8 = idx & 7;
            CP_ASYNC16(sbase + bufo + GM_BH + row*144 + q8*16,
                       &Bh[(size_t)(n0+row)*512 + kbase + q8*8]);
        }
        CP_COMMIT();
    };

    issue_chunk(0, 0);

    for (int kb = 0; kb < 8; kb++) {
        uint32_t bufo = (kb & 1) ? GM_BUF : 0;
        CP_WAIT0();
        __syncthreads();
        if (kb + 1 < 8)
            issue_chunk(kb + 1, ((kb + 1) & 1) ? GM_BUF : 0);

        #pragma unroll
        for (int ks = 0; ks < 4; ks++) {
            uint32_t a_hi[2][4], a_lo[2][4], b_hi[8];
            #pragma unroll
            for (int mi = 0; mi < 2; mi++) {
                int row = wm*32 + mi*16 + (lane & 15);
                int kcol = ks*16 + ((lane >> 4) << 3);
                uint32_t off = bufo + (uint32_t)(row*144 + kcol*2);
                ldsm_x4(a_hi[mi][0], a_hi[mi][1], a_hi[mi][2], a_hi[mi][3],
                        sbase + GM_AH + off);
                ldsm_x4(a_lo[mi][0], a_lo[mi][1], a_lo[mi][2], a_lo[mi][3],
                        sbase + GM_AL + off);
            }
            #pragma unroll
            for (int g = 0; g < 2; g++) {
                int rr = lane & 7;
                int hk = (lane >> 3) & 1;
                int hn = (lane >> 4) & 1;
                int nrow = wn*32 + g*16 + hn*8 + rr;
                int kcol = ks*16 + hk*8;
                uint32_t off = bufo + (uint32_t)(nrow*144 + kcol*2);
                ldsm_x4(b_hi[g*4+0], b_hi[g*4+1], b_hi[g*4+2], b_hi[g*4+3],
                        sbase + GM_BH + off);
            }
            #pragma unroll
            for (int mi = 0; mi < 2; mi++)
                #pragma unroll
                for (int ni = 0; ni < 4; ni++) {
                    mma_f16(acc[mi][ni], a_hi[mi], &b_hi[ni*2]);
                    mma_f16(acc[mi][ni], a_lo[mi], &b_hi[ni*2]);
                }
        }
    }

    #pragma unroll
    for (int mi = 0; mi < 2; mi++) {
        #pragma unroll
        for (int ni = 0; ni < 4; ni++) {
            int nl = wn*32 + ni*8 + (lane & 3)*2;
            float b0 = bo[n0 + nl], b1 = bo[n0 + nl + 1];
            #pragma unroll
            for (int half = 0; half < 2; half++) {
                int m = row0 + wm*32 + mi*16 + (lane >> 2) + half*8;
                float2 o;
                o.x = acc[mi][ni][half*2+0] + b0;
                o.y = acc[mi][ni][half*2+1] + b1;
                *(float2*)&outp[(size_t)m*D_ + n0 + nl] = o;
            }
        }
    }
}

// ===========================================================================
// Flash attention v4: R13/R15 blocking (32 q-rows/warp, 128/CTA, 2 CTA/SM)
// + mb prefetched as raw half2 words before QK MMAs (hidden latency);
// Q hi AND lo fragments reloaded from smem per k-step (regs traded for mbr).
// ===========================================================================
#define AT_BUF  18432
#define AT_KH   0
#define AT_VH   9216
#define AT_Q    36864
#define AT_QL   (36864 + 18432)
#define AT_SMEM 73728

__global__ __launch_bounds__(128) void attn_mma_kernel()
{
    extern __shared__ __align__(16) unsigned char smem[];
    uint32_t sbase = smem_u32(smem);

    int tid = threadIdx.x;
    int wid = tid >> 5, lane = tid & 31;
    int r = lane >> 2, cq = lane & 3;

    int qt = blockIdx.x, bh = blockIdx.y, dir = blockIdx.z;
    int b = bh >> 3, h = bh & 7;
    int enc_q = dir, enc_kv = 1 - dir;

    size_t qoff  = ((size_t)((enc_q *B_ + b)*H_ + h))*L_*HD_;
    size_t kvoff = ((size_t)((enc_kv*B_ + b)*H_ + h))*L_*HD_;
    const unsigned short* Qh = g_qh + qoff;
    const unsigned short* Ql = g_ql + qoff;
    const unsigned short* Kh = g_kh + kvoff;
    const unsigned short* Vh = g_vh + kvoff;
    const unsigned short* mb = g_mb + ((size_t)dir*B_ + b)*L_*L_;
    int q0 = qt * 128;

    #pragma unroll
    for (int i = 0; i < 16; i++) {
        int idx = i*128 + tid;
        int a = idx >> 10;
        int rem = idx & 1023;
        int row = rem >> 3, q8 = rem & 7;
        const unsigned short* srcp = a ? Ql : Qh;
        CP_ASYNC16(sbase + (a ? AT_QL : AT_Q) + row*144 + q8*16,
                   &srcp[(size_t)(q0+row)*HD_ + q8*8]);
    }
    CP_COMMIT();

    auto issue_kv = [&](int t, uint32_t bufo) {
        int k0 = t * 64;
        #pragma unroll
        for (int i = 0; i < 8; i++) {
            int idx = i*128 + tid;
            int a = idx >> 9;
            int rem = idx & 511;
            int row = rem >> 3, q8 = rem & 7;
            const unsigned short* srcp = a ? Vh : Kh;
            int dsto = a ? AT_VH : AT_KH;
            CP_ASYNC16(sbase + bufo + dsto + row*144 + q8*16,
                       &srcp[(size_t)(k0+row)*HD_ + q8*8]);
        }
        CP_COMMIT();
    };

    issue_kv(0, 0);

    float o_acc[2][8][4];
    #pragma unroll
    for (int mt = 0; mt < 2; mt++)
        #pragma unroll
        for (int nt = 0; nt < 8; nt++)
            #pragma unroll
            for (int c = 0; c < 4; c++) o_acc[mt][nt][c] = 0.f;
    float mreg[2][2], lreg[2][2];
    #pragma unroll
    for (int mt = 0; mt < 2; mt++) {
        mreg[mt][0] = -3.0e38f; mreg[mt][1] = -3.0e38f;
        lreg[mt][0] = 0.f;      lreg[mt][1] = 0.f;
    }

    int qgw = q0 + wid*32 + r;
    const unsigned short* mbrow[2][2];
    #pragma unroll
    for (int mt = 0; mt < 2; mt++) {
        mbrow[mt][0] = mb + (size_t)(qgw + mt*16)*L_ + cq*2;
        mbrow[mt][1] = mb + (size_t)(qgw + mt*16 + 8)*L_ + cq*2;
    }

    for (int t = 0; t < 16; t++) {
        int k0 = t * 64;
        uint32_t bufo = (t & 1) ? AT_BUF : 0;
        CP_WAIT0();
        __syncthreads();
        if (t + 1 < 16)
            issue_kv(t + 1, ((t + 1) & 1) ? AT_BUF : 0);

        // ---- prefetch mask+bias as raw half2 words (hidden under QK) ----
        uint32_t mbr[2][2][8];
        #pragma unroll
        for (int mt = 0; mt < 2; mt++)
            #pragma unroll
            for (int rp = 0; rp < 2; rp++)
                #pragma unroll
                for (int nt = 0; nt < 8; nt++)
                    mbr[mt][rp][nt] =
                        *(const uint32_t*)&mbrow[mt][rp][k0 + nt*8];

        // ---- S = Q K^T : Q hi/lo reloaded per ks; B shared by mt ----
        float s_acc[2][8][4];
        #pragma unroll
        for (int mt = 0; mt < 2; mt++)
            #pragma unroll
            for (int nt = 0; nt < 8; nt++)
                #pragma unroll
                for (int c = 0; c < 4; c++) s_acc[mt][nt][c] = 0.f;

        #pragma unroll
        for (int ks = 0; ks < 4; ks++) {
            uint32_t aq_h[2][4], aq_l[2][4];
            #pragma unroll
            for (int mt = 0; mt < 2; mt++) {
                int row = wid*32 + mt*16 + (lane & 15);
                int kcol = ks*16 + ((lane >> 4) << 3);
                uint32_t qoff2 = (uint32_t)(row*144 + kcol*2);
                ldsm_x4(aq_h[mt][0], aq_h[mt][1], aq_h[mt][2], aq_h[mt][3],
                        sbase + AT_Q + qoff2);
                ldsm_x4(aq_l[mt][0], aq_l[mt][1], aq_l[mt][2], aq_l[mt][3],
                        sbase + AT_QL + qoff2);
            }
            #pragma unroll
            for (int g = 0; g < 4; g++) {
                uint32_t bk[4];
                int rr = lane & 7;
                int hk = (lane >> 3) & 1;
                int hn = (lane >> 4) & 1;
                int nrow = g*16 + hn*8 + rr;
                int kcol = ks*16 + hk*8;
                uint32_t off = bufo + (uint32_t)(nrow*144 + kcol*2);
                ldsm_x4(bk[0], bk[1], bk[2], bk[3], sbase + AT_KH + off);
                int n0t = g*2, n1t = g*2 + 1;
                #pragma unroll
                for (int mt = 0; mt < 2; mt++) {
                    mma_f16(s_acc[mt][n0t], aq_h[mt], &bk[0]);
                    mma_f16(s_acc[mt][n1t], aq_h[mt], &bk[2]);
                    mma_f16(s_acc[mt][n0t], aq_l[mt], &bk[0]);
                    mma_f16(s_acc[mt][n1t], aq_l[mt], &bk[2]);
                }
            }
        }

        // ---- mask+bias add (from prefetched regs) + softmax per m-tile ----
        #pragma unroll
        for (int mt = 0; mt < 2; mt++) {
            #pragma unroll
            for (int nt = 0; nt < 8; nt++) {
                float2 b0v = h2unpack(mbr[mt][0][nt]);
                float2 b1v = h2unpack(mbr[mt][1][nt]);
                s_acc[mt][nt][0] += b0v.x;
                s_acc[mt][nt][1] += b0v.y;
                s_acc[mt][nt][2] += b1v.x;
                s_acc[mt][nt][3] += b1v.y;
            }

            float mx0 = -3.0e38f, mx1 = -3.0e38f;
            #pragma unroll
            for (int nt = 0; nt < 8; nt++) {
                mx0 = fmaxf(mx0, fmaxf(s_acc[mt][nt][0], s_acc[mt][nt][1]));
                mx1 = fmaxf(mx1, fmaxf(s_acc[mt][nt][2], s_acc[mt][nt][3]));
            }
            mx0 = fmaxf(mx0, __shfl_xor_sync(0xffffffffu, mx0, 1));
            mx0 = fmaxf(mx0, __shfl_xor_sync(0xffffffffu, mx0, 2));
            mx1 = fmaxf(mx1, __shfl_xor_sync(0xffffffffu, mx1, 1));
            mx1 = fmaxf(mx1, __shfl_xor_sync(0xffffffffu, mx1, 2));

            float mn0 = fmaxf(mreg[mt][0], mx0);
            float mn1 = fmaxf(mreg[mt][1], mx1);
            float c0 = ex2f(mreg[mt][0] - mn0);
            float c1 = ex2f(mreg[mt][1] - mn1);
            mreg[mt][0] = mn0; mreg[mt][1] = mn1;

            float rs0 = 0.f, rs1 = 0.f;
            #pragma unroll
            for (int nt = 0; nt < 8; nt++) {
                s_acc[mt][nt][0] = ex2f(s_acc[mt][nt][0] - mn0); rs0 += s_acc[mt][nt][0];
                s_acc[mt][nt][1] = ex2f(s_acc[mt][nt][1] - mn0); rs0 += s_acc[mt][nt][1];
                s_acc[mt][nt][2] = ex2f(s_acc[mt][nt][2] - mn1); rs1 += s_acc[mt][nt][2];
                s_acc[mt][nt][3] = ex2f(s_acc[mt][nt][3] - mn1); rs1 += s_acc[mt][nt][3];
            }
            rs0 += __shfl_xor_sync(0xffffffffu, rs0, 1);
            rs0 += __shfl_xor_sync(0xffffffffu, rs0, 2);
            rs1 += __shfl_xor_sync(0xffffffffu, rs1, 1);
            rs1 += __shfl_xor_sync(0xffffffffu, rs1, 2);
            lreg[mt][0] = lreg[mt][0]*c0 + rs0;
            lreg[mt][1] = lreg[mt][1]*c1 + rs1;

            #pragma unroll
            for (int nt = 0; nt < 8; nt++) {
                o_acc[mt][nt][0] *= c0; o_acc[mt][nt][1] *= c0;
                o_acc[mt][nt][2] *= c1; o_acc[mt][nt][3] *= c1;
            }
        }

        // ---- O += P V : shared V-frags across m-tiles ----
        #pragma unroll
        for (int ks = 0; ks < 4; ks++) {
            int t0 = 2*ks, t1 = 2*ks + 1;
            uint32_t ap[2][4];
            #pragma unroll
            for (int mt = 0; mt < 2; mt++) {
                ap[mt][0] = pack2h(s_acc[mt][t0][0], s_acc[mt][t0][1]);
                ap[mt][1] = pack2h(s_acc[mt][t0][2], s_acc[mt][t0][3]);
                ap[mt][2] = pack2h(s_acc[mt][t1][0], s_acc[mt][t1][1]);
                ap[mt][3] = pack2h(s_acc[mt][t1][2], s_acc[mt][t1][3]);
            }
            #pragma unroll
            for (int g = 0; g < 4; g++) {
                uint32_t bv[4];
                int kk  = ks*16 + ((lane >> 3) & 1)*8 + (lane & 7);
                int hdo = g*16 + ((lane >> 4) & 1)*8;
                uint32_t off = bufo + (uint32_t)(kk*144 + hdo*2);
                ldsm_x4_t(bv[0], bv[1], bv[2], bv[3], sbase + AT_VH + off);
                int n0t = g*2, n1t = g*2 + 1;
                #pragma unroll
                for (int mt = 0; mt < 2; mt++) {
                    mma_f16(o_acc[mt][n0t], ap[mt], &bv[0]);
                    mma_f16(o_acc[mt][n1t], ap[mt], &bv[2]);
                }
            }
        }
    }

    // ---- finalize: ctx = O/l as fp16 hi/lo ----
    #pragma unroll
    for (int mt = 0; mt < 2; mt++) {
        float inv0 = 1.f / lreg[mt][0];
        float inv1 = 1.f / lreg[mt][1];
        int row0g = qgw + mt*16;
        size_t base0 = ((size_t)(enc_q*B_ + b)*L_ + row0g)*D_ + h*64 + cq*2;
        size_t base1 = ((size_t)(enc_q*B_ + b)*L_ + row0g + 8)*D_ + h*64 + cq*2;
        #pragma unroll
        for (int nt = 0; nt < 8; nt++) {
            uint32_t hi0, lo0, hi1, lo1;
            split2(o_acc[mt][nt][0]*inv0, o_acc[mt][nt][1]*inv0, hi0, lo0);
            split2(o_acc[mt][nt][2]*inv1, o_acc[mt][nt][3]*inv1, hi1, lo1);
            *(uint32_t*)&g_ch[base0 + nt*8] = hi0;
            *(uint32_t*)&g_cl[base0 + nt*8] = lo0;
            *(uint32_t*)&g_ch[base1 + nt*8] = hi1;
            *(uint32_t*)&g_cl[base1 + nt*8] = lo1;
        }
    }
}

// ---------------------------------------------------------------------------
extern "C" void kernel_launch(void* const* d_in, const int* in_sizes, int n_in,
                              void* d_out, int out_size)
{
    const float* u_enc     = (const float*)d_in[0];
    const float* e_enc     = (const float*)d_in[1];
    const float* logit_bpp = (const float*)d_in[2];
    const void*  ue_mask   = d_in[3];
    const void*  eu_mask   = d_in[4];
    const float* wq_k = (const float*)d_in[5];
    const float* wq_b = (const float*)d_in[6];
    const float* wk_k = (const float*)d_in[7];
    const float* wk_b = (const float*)d_in[8];
    const float* wv_k = (const float*)d_in[9];
    const float* wv_b = (const float*)d_in[10];
    const float* wo_k = (const float*)d_in[11];
    const float* wo_b = (const float*)d_in[12];
    const float* bpp_w = (const float*)d_in[13];
    const float* bpp_b = (const float*)d_in[14];
    float* out = (float*)d_out;

    cudaFuncSetAttribute((const void*)attn_mma_kernel,
                         cudaFuncAttributeMaxDynamicSharedMemorySize, AT_SMEM);
    cudaFuncSetAttribute((const void*)qkv_mma_kernel,
                         cudaFuncAttributeMaxDynamicSharedMemorySize, QG_SMEM);
    cudaFuncSetAttribute((const void*)oproj_mma_kernel,
                         cudaFuncAttributeMaxDynamicSharedMemorySize, GM_SMEM);

    // 0) mask dtype detection
    mask_detect_kernel<<<1, 256>>>((const unsigned int*)ue_mask);
    // 1) fused prep
    prep_kernel<<<5120, 256>>>(logit_bpp, bpp_w, bpp_b, ue_mask, eu_mask,
                               u_enc, e_enc, wq_k, wk_k, wv_k, wo_k);
    // 2) fused QKV projection
    qkv_mma_kernel<<<dim3(8, 64), 256, QG_SMEM>>>(wq_b, wk_b, wv_b);
    // 3) fused attention (mb prefetch under QK MMAs)
    attn_mma_kernel<<<dim3(8, 32, 2), 128, AT_SMEM>>>();
    // 4) output projection -> d_out
    oproj_mma_kernel<<<dim3(8, 64), 256, GM_SMEM>>>(wo_b, out);
}

// round 17
// speedup vs baseline: 1.2595x; 1.0666x over previous
#include <cuda_runtime.h>
#include <cuda_fp16.h>
#include <math.h>
#include <float.h>
#include <stdint.h>
#include <string.h>

#define B_  4
#define L_  1024
#define D_  512
#define H_  8
#define HD_ 64
#define PROJ_ELEMS (2*B_*H_*L_*HD_)   /* 4,194,304 */
#define MASK_ELEMS ((size_t)B_*L_*L_) /* 4,194,304 */
#define ENC_ELEMS  (8192*512)
#define LOG2E_F 1.4426950408889634f

// producer-split fp16 storage
__device__ unsigned short g_ah[ENC_ELEMS], g_al[ENC_ELEMS];      // [u;e] inputs
__device__ unsigned short g_wth[4*512*512], g_wtl[4*512*512];    // W^T, n-major
__device__ unsigned short g_qh[PROJ_ELEMS], g_ql[PROJ_ELEMS];    // Q hi/lo
__device__ unsigned short g_kh[PROJ_ELEMS];                      // K single fp16
__device__ unsigned short g_vh[PROJ_ELEMS];                      // V single fp16
__device__ unsigned short g_ch[PROJ_ELEMS];                      // ctx single fp16
__device__ unsigned short g_mb[2*B_*L_*L_];  // fp16 (bias*log2e) | -30000 masked
__device__ int g_mtype;

// ===========================================================================
// helpers
// ===========================================================================
__device__ __forceinline__ uint32_t smem_u32(const void* p) {
    uint32_t a;
    asm("{ .reg .u64 t; cvta.to.shared.u64 t, %1; cvt.u32.u64 %0, t; }"
        : "=r"(a) : "l"(p));
    return a;
}
#define CP_ASYNC16(saddr, gptr) \
    asm volatile("cp.async.ca.shared.global [%0], [%1], 16;" \
                 :: "r"(saddr), "l"(gptr))
#define CP_COMMIT() asm volatile("cp.async.commit_group;" ::: "memory")
#define CP_WAIT0()  asm volatile("cp.async.wait_group 0;" ::: "memory")

__device__ __forceinline__ float ex2f(float x) {
    float r;
    asm("ex2.approx.f32 %0, %1;" : "=f"(r) : "f"(x));
    return r;
}
__device__ __forceinline__ void ldsm_x4(uint32_t& r0, uint32_t& r1,
                                        uint32_t& r2, uint32_t& r3,
                                        uint32_t addr) {
    asm volatile("ldmatrix.sync.aligned.m8n8.x4.shared.b16 {%0,%1,%2,%3}, [%4];"
                 : "=r"(r0), "=r"(r1), "=r"(r2), "=r"(r3) : "r"(addr));
}
__device__ __forceinline__ void ldsm_x4_t(uint32_t& r0, uint32_t& r1,
                                          uint32_t& r2, uint32_t& r3,
                                          uint32_t addr) {
    asm volatile("ldmatrix.sync.aligned.m8n8.x4.trans.shared.b16 {%0,%1,%2,%3}, [%4];"
                 : "=r"(r0), "=r"(r1), "=r"(r2), "=r"(r3) : "r"(addr));
}
__device__ __forceinline__ void mma_f16(float* c, const uint32_t* a,
                                        const uint32_t* b) {
    asm volatile("mma.sync.aligned.m16n8k16.row.col.f32.f16.f16.f32 "
                 "{%0,%1,%2,%3}, {%4,%5,%6,%7}, {%8,%9}, {%0,%1,%2,%3};"
                 : "+f"(c[0]), "+f"(c[1]), "+f"(c[2]), "+f"(c[3])
                 : "r"(a[0]), "r"(a[1]), "r"(a[2]), "r"(a[3]),
                   "r"(b[0]), "r"(b[1]));
}
__device__ __forceinline__ unsigned short f2h_bits(float x) {
    __half h = __float2half_rn(x);
    unsigned short u; memcpy(&u, &h, 2); return u;
}
__device__ __forceinline__ float hbits2f(unsigned short u) {
    __half h; memcpy(&h, &u, 2); return __half2float(h);
}
__device__ __forceinline__ void split2(float x, float y, uint32_t& hi, uint32_t& lo) {
    unsigned short hx = f2h_bits(x), hy = f2h_bits(y);
    unsigned short lx = f2h_bits(x - hbits2f(hx));
    unsigned short ly = f2h_bits(y - hbits2f(hy));
    hi = (uint32_t)hx | ((uint32_t)hy << 16);
    lo = (uint32_t)lx | ((uint32_t)ly << 16);
}
__device__ __forceinline__ uint32_t pack2h(float x, float y) {
    return (uint32_t)f2h_bits(x) | ((uint32_t)f2h_bits(y) << 16);
}
__device__ __forceinline__ float2 h2unpack(uint32_t w) {
    __half2 h; memcpy(&h, &w, 4);
    return __half22float2(h);
}

// ===========================================================================
// Mask dtype detection
// ===========================================================================
__global__ void mask_detect_kernel(const unsigned int* __restrict__ m)
{
    __shared__ int viol[3];
    if (threadIdx.x < 3) viol[threadIdx.x] = 0;
    __syncthreads();
    int v0 = 0, v1 = 0, v2 = 0;
    for (int i = threadIdx.x; i < 16384; i += 256) {
        unsigned w = m[i];
        if (w > 1u) v0 = 1;
        if (w != 0u && w != 0x3F800000u) v1 = 1;
        if (w != 0u && w != 0x3F800000u && w != 0x00003F80u && w != 0x3F803F80u) v2 = 1;
    }
    if (v0) atomicOr(&viol[0], 1);
    if (v1) atomicOr(&viol[1], 1);
    if (v2) atomicOr(&viol[2], 1);
    __syncthreads();
    if (threadIdx.x == 0) {
        int t;
        if      (!viol[0]) t = 1;
        else if (!viol[1]) t = 2;
        else if (!viol[2]) t = 3;
        else               t = 0;
        g_mtype = t;
    }
}

// ===========================================================================
// Fused prep: blocks [0,2048) maskbias, [2048,4096) enc split, [4096,5120) wt.
// ===========================================================================
__global__ __launch_bounds__(256) void prep_kernel(
    const float* __restrict__ lb,
    const float* __restrict__ wp, const float* __restrict__ bp,
    const void* __restrict__ ue, const void* __restrict__ eu,
    const float* __restrict__ u, const float* __restrict__ e,
    const float* __restrict__ wq, const float* __restrict__ wk,
    const float* __restrict__ wv, const float* __restrict__ wo)
{
    __shared__ float s[32][33];
    int bx = blockIdx.x;
    int tid = threadIdx.x;
    int tx = tid & 31, ty = tid >> 5;

    if (bx < 2048) {
        int dir = bx >> 10;
        int q0 = ((bx >> 5) & 31) * 32;
        int k0 = (bx & 31) * 32;
        int mt = g_mtype;
        float w = wp[0] * LOG2E_F, bb = bp[0] * LOG2E_F;
        const void* msk = dir ? eu : ue;
        unsigned short* dst = g_mb + (size_t)dir * MASK_ELEMS;

        if (dir == 1) {
            #pragma unroll
            for (int i = ty; i < 32; i += 8)
                s[i][tx] = lb[(size_t)(k0+i)*L_ + q0 + tx];
            __syncthreads();
        }
        unsigned short mk = f2h_bits(-30000.0f);
        #pragma unroll
        for (int i = ty; i < 32; i += 8) {
            float bias;
            if (dir == 0) bias = fmaf(w, lb[(size_t)(q0+i)*L_ + k0 + tx], bb);
            else          bias = fmaf(w, s[tx][i], bb);
            unsigned short bh = f2h_bits(bias);
            size_t rowoff = (size_t)(q0+i)*L_ + k0 + tx;
            #pragma unroll
            for (int b = 0; b < B_; b++) {
                size_t idx = ((size_t)b << 20) + rowoff;
                bool mv;
                if      (mt == 1) mv = ((const int*)msk)[idx] != 0;
                else if (mt == 2) mv = ((const float*)msk)[idx] != 0.f;
                else if (mt == 3) mv = ((const unsigned short*)msk)[idx] != 0;
                else              mv = ((const unsigned char*)msk)[idx] != 0;
                dst[idx] = mv ? bh : mk;
            }
        }
    } else if (bx < 4096) {
        int idx = bx - 2048;
        int z = idx >> 10, blk = idx & 1023;
        const float* src = z ? e : u;
        size_t base4 = (size_t)z * (4096*512/4);
        size_t stride = 1024u * 256u;
        for (size_t i4 = (size_t)blk*256 + tid; i4 < 4096*512/4; i4 += stride) {
            float4 v = ((const float4*)src)[i4];
            uint32_t h01, l01, h23, l23;
            split2(v.x, v.y, h01, l01);
            split2(v.z, v.w, h23, l23);
            ((uint2*)g_ah)[base4 + i4] = make_uint2(h01, h23);
            ((uint2*)g_al)[base4 + i4] = make_uint2(l01, l23);
        }
    } else {
        int idx = bx - 4096;
        int z = idx >> 8, by = (idx >> 4) & 15, bxx = idx & 15;
        const float* src = (z == 0) ? wq : (z == 1) ? wk : (z == 2) ? wv : wo;
        int x  = bxx*32 + tx;
        int y0 = by*32;
        #pragma unroll
        for (int i = ty; i < 32; i += 8)
            s[i][tx] = src[(size_t)(y0+i)*512 + x];
        __syncthreads();
        size_t base = (size_t)z * 512*512;
        int ko = y0 + tx;
        #pragma unroll
        for (int i = ty; i < 32; i += 8) {
            float v = s[tx][i];
            unsigned short h = f2h_bits(v);
            unsigned short l = f2h_bits(v - hbits2f(h));
            size_t widx = base + (size_t)(bxx*32+i)*512 + ko;
            g_wth[widx] = h;
            g_wtl[widx] = l;
        }
    }
}

// ===========================================================================
// Fused QKV GEMM (unchanged from R16)
// ===========================================================================
#define QG_BUF  73728
#define QG_AH   0
#define QG_AL   18432
#define QG_BQH  36864
#define QG_BQL  46080
#define QG_BKH  55296
#define QG_BVH  64512
#define QG_SMEM 147456

__global__ __launch_bounds__(256) void qkv_mma_kernel(
    const float* __restrict__ bq, const float* __restrict__ bk,
    const float* __restrict__ bv)
{
    extern __shared__ __align__(16) unsigned char smem[];
    uint32_t sbase = smem_u32(smem);

    int tid = threadIdx.x;
    int wid = tid >> 5, lane = tid & 31;
    int wm = wid & 3, wn = wid >> 2;

    const unsigned short* Bqh = g_wth;
    const unsigned short* Bql = g_wtl;
    const unsigned short* Bkh = g_wth + (size_t)1*512*512;
    const unsigned short* Bvh = g_wth + (size_t)2*512*512;

    int n0   = blockIdx.x * 64;
    int row0 = blockIdx.y * 128;

    float accq[2][4][4], acck[2][4][4], accv[2][4][4];
    #pragma unroll
    for (int mi = 0; mi < 2; mi++)
        #pragma unroll
        for (int ni = 0; ni < 4; ni++)
            #pragma unroll
            for (int c = 0; c < 4; c++) {
                accq[mi][ni][c] = 0.f;
                acck[mi][ni][c] = 0.f;
                accv[mi][ni][c] = 0.f;
            }

    auto issue_chunk = [&](int kb, uint32_t bufo) {
        int kbase = kb * 64;
        #pragma unroll
        for (int i = 0; i < 8; i++) {
            int idx = i*256 + tid;
            int a = idx >> 10;
            int rem = idx & 1023;
            int row = rem >> 3, q8 = rem & 7;
            const unsigned short* srcp = a ? g_al : g_ah;
            CP_ASYNC16(sbase + bufo + (a ? QG_AL : QG_AH) + row*144 + q8*16,
                       &srcp[(size_t)(row0+row)*512 + kbase + q8*8]);
        }
        #pragma unroll
        for (int i = 0; i < 8; i++) {
            int idx = i*256 + tid;
            int a = idx >> 9;
            int rem = idx & 511;
            int row = rem >> 3, q8 = rem & 7;
            const unsigned short* srcp = (a == 0) ? Bqh : (a == 1) ? Bql
                                       : (a == 2) ? Bkh : Bvh;
            int dsto = (a == 0) ? QG_BQH : (a == 1) ? QG_BQL
                     : (a == 2) ? QG_BKH : QG_BVH;
            CP_ASYNC16(sbase + bufo + dsto + row*144 + q8*16,
                       &srcp[(size_t)(n0+row)*512 + kbase + q8*8]);
        }
        CP_COMMIT();
    };

    issue_chunk(0, 0);

    for (int kb = 0; kb < 8; kb++) {
        uint32_t bufo = (kb & 1) ? QG_BUF : 0;
        CP_WAIT0();
        __syncthreads();
        if (kb + 1 < 8)
            issue_chunk(kb + 1, ((kb + 1) & 1) ? QG_BUF : 0);

        #pragma unroll
        for (int ks = 0; ks < 4; ks++) {
            uint32_t a_hi[2][4], a_lo[2][4];
            #pragma unroll
            for (int mi = 0; mi < 2; mi++) {
                int row = wm*32 + mi*16 + (lane & 15);
                int kcol = ks*16 + ((lane >> 4) << 3);
                uint32_t off = bufo + (uint32_t)(row*144 + kcol*2);
                ldsm_x4(a_hi[mi][0], a_hi[mi][1], a_hi[mi][2], a_hi[mi][3],
                        sbase + QG_AH + off);
                ldsm_x4(a_lo[mi][0], a_lo[mi][1], a_lo[mi][2], a_lo[mi][3],
                        sbase + QG_AL + off);
            }
            #pragma unroll
            for (int g = 0; g < 2; g++) {
                int rr = lane & 7;
                int hk = (lane >> 3) & 1;
                int hn = (lane >> 4) & 1;
                int nrow = wn*32 + g*16 + hn*8 + rr;
                int kcol = ks*16 + hk*8;
                uint32_t off = bufo + (uint32_t)(nrow*144 + kcol*2);
                uint32_t bqh[4], bql[4], bkh[4], bvh[4];
                ldsm_x4(bqh[0], bqh[1], bqh[2], bqh[3], sbase + QG_BQH + off);
                ldsm_x4(bql[0], bql[1], bql[2], bql[3], sbase + QG_BQL + off);
                ldsm_x4(bkh[0], bkh[1], bkh[2], bkh[3], sbase + QG_BKH + off);
                ldsm_x4(bvh[0], bvh[1], bvh[2], bvh[3], sbase + QG_BVH + off);
                #pragma unroll
                for (int sub = 0; sub < 2; sub++) {
                    int ni = g*2 + sub;
                    #pragma unroll
                    for (int mi = 0; mi < 2; mi++) {
                        mma_f16(accq[mi][ni], a_hi[mi], &bqh[sub*2]);
                        mma_f16(accq[mi][ni], a_lo[mi], &bqh[sub*2]);
                        mma_f16(accq[mi][ni], a_hi[mi], &bql[sub*2]);
                        mma_f16(acck[mi][ni], a_hi[mi], &bkh[sub*2]);
                        mma_f16(acck[mi][ni], a_lo[mi], &bkh[sub*2]);
                        mma_f16(accv[mi][ni], a_hi[mi], &bvh[sub*2]);
                        mma_f16(accv[mi][ni], a_lo[mi], &bvh[sub*2]);
                    }
                }
            }
        }
    }

    float qscale = 0.125f * LOG2E_F;
    #pragma unroll
    for (int mi = 0; mi < 2; mi++) {
        #pragma unroll
        for (int ni = 0; ni < 4; ni++) {
            int nl = wn*32 + ni*8 + (lane & 3)*2;
            float bq0 = bq[n0 + nl], bq1 = bq[n0 + nl + 1];
            float bk0 = bk[n0 + nl], bk1 = bk[n0 + nl + 1];
            float bv0 = bv[n0 + nl], bv1 = bv[n0 + nl + 1];
            #pragma unroll
            for (int half = 0; half < 2; half++) {
                int m = row0 + wm*32 + mi*16 + (lane >> 2) + half*8;
                int enc = m >> 12, b = (m >> 10) & 3, l = m & 1023;
                int h = n0 >> 6;
                size_t idx = ((((size_t)(enc*B_ + b))*H_ + h)*L_ + l)*HD_ + nl;
                float qx = (accq[mi][ni][half*2+0] + bq0) * qscale;
                float qy = (accq[mi][ni][half*2+1] + bq1) * qscale;
                uint32_t hi, lo; split2(qx, qy, hi, lo);
                *(uint32_t*)&g_qh[idx] = hi;
                *(uint32_t*)&g_ql[idx] = lo;
                *(uint32_t*)&g_kh[idx] = pack2h(acck[mi][ni][half*2+0] + bk0,
                                                acck[mi][ni][half*2+1] + bk1);
                *(uint32_t*)&g_vh[idx] = pack2h(accv[mi][ni][half*2+0] + bv0,
                                                accv[mi][ni][half*2+1] + bv1);
            }
        }
    }
}

// ===========================================================================
// Out-proj GEMM: ctx (single fp16) x wo (hi), 1-term, fp32 out. 128M x 64N.
// Stage: A 18432 + B 9216 = 27648; double-buffered 55296 -> up to 4 CTA/SM.
// ===========================================================================
#define GM_BUF  27648
#define GM_A    0
#define GM_BH   18432
#define GM_SMEM 55296

__global__ __launch_bounds__(256) void oproj_mma_kernel(
    const float* __restrict__ bo, float* __restrict__ outp)
{
    extern __shared__ __align__(16) unsigned char smem[];
    uint32_t sbase = smem_u32(smem);

    int tid = threadIdx.x;
    int wid = tid >> 5, lane = tid & 31;
    int wm = wid & 3, wn = wid >> 2;

    const unsigned short* Bh = g_wth + (size_t)3*512*512;
    int n0   = blockIdx.x * 64;
    int row0 = blockIdx.y * 128;

    float acc[2][4][4];
    #pragma unroll
    for (int mi = 0; mi < 2; mi++)
        #pragma unroll
        for (int ni = 0; ni < 4; ni++)
            #pragma unroll
            for (int c = 0; c < 4; c++) acc[mi][ni][c] = 0.f;

    auto issue_chunk = [&](int kb, uint32_t bufo) {
        int kbase = kb * 64;
        // A: 128 rows x 8 uint4 = 1024 / 256 = 4 iters
        #pragma unroll
        for (int i = 0; i < 4; i++) {
            int idx = i*256 + tid;
            int row = idx >> 3, q8 = idx & 7;
            CP_ASYNC16(sbase + bufo + GM_A + row*144 + q8*16,
                       &g_ch[(size_t)(row0+row)*512 + kbase + q8*8]);
        }
        // B: 64 rows x 8 uint4 = 512 / 256 = 2 iters
        #pragma unroll
        for (int i = 0; i < 2; i++) {
            int idx = i*256 + tid;
            int row = idx >> 3, q8 = idx & 7;
            CP_ASYNC16(sbase + bufo + GM_BH + row*144 + q8*16,
                       &Bh[(size_t)(n0+row)*512 + kbase + q8*8]);
        }
        CP_COMMIT();
    };

    issue_chunk(0, 0);

    for (int kb = 0; kb < 8; kb++) {
        uint32_t bufo = (kb & 1) ? GM_BUF : 0;
        CP_WAIT0();
        __syncthreads();
        if (kb + 1 < 8)
            issue_chunk(kb + 1, ((kb + 1) & 1) ? GM_BUF : 0);

        #pragma unroll
        for (int ks = 0; ks < 4; ks++) {
            uint32_t a_f[2][4], b_hi[8];
            #pragma unroll
            for (int mi = 0; mi < 2; mi++) {
                int row = wm*32 + mi*16 + (lane & 15);
                int kcol = ks*16 + ((lane >> 4) << 3);
                uint32_t off = bufo + (uint32_t)(row*144 + kcol*2);
                ldsm_x4(a_f[mi][0], a_f[mi][1], a_f[mi][2], a_f[mi][3],
                        sbase + GM_A + off);
            }
            #pragma unroll
            for (int g = 0; g < 2; g++) {
                int rr = lane & 7;
                int hk = (lane >> 3) & 1;
                int hn = (lane >> 4) & 1;
                int nrow = wn*32 + g*16 + hn*8 + rr;
                int kcol = ks*16 + hk*8;
                uint32_t off = bufo + (uint32_t)(nrow*144 + kcol*2);
                ldsm_x4(b_hi[g*4+0], b_hi[g*4+1], b_hi[g*4+2], b_hi[g*4+3],
                        sbase + GM_BH + off);
            }
            #pragma unroll
            for (int mi = 0; mi < 2; mi++)
                #pragma unroll
                for (int ni = 0; ni < 4; ni++)
                    mma_f16(acc[mi][ni], a_f[mi], &b_hi[ni*2]);
        }
    }

    #pragma unroll
    for (int mi = 0; mi < 2; mi++) {
        #pragma unroll
        for (int ni = 0; ni < 4; ni++) {
            int nl = wn*32 + ni*8 + (lane & 3)*2;
            float b0 = bo[n0 + nl], b1 = bo[n0 + nl + 1];
            #pragma unroll
            for (int half = 0; half < 2; half++) {
                int m = row0 + wm*32 + mi*16 + (lane >> 2) + half*8;
                float2 o;
                o.x = acc[mi][ni][half*2+0] + b0;
                o.y = acc[mi][ni][half*2+1] + b1;
                *(float2*)&outp[(size_t)m*D_ + n0 + nl] = o;
            }
        }
    }
}

// ===========================================================================
// Flash attention (R16 config; finalize writes ctx single fp16)
// ===========================================================================
#define AT_BUF  18432
#define AT_KH   0
#define AT_VH   9216
#define AT_Q    36864
#define AT_QL   (36864 + 18432)
#define AT_SMEM 73728

__global__ __launch_bounds__(128) void attn_mma_kernel()
{
    extern __shared__ __align__(16) unsigned char smem[];
    uint32_t sbase = smem_u32(smem);

    int tid = threadIdx.x;
    int wid = tid >> 5, lane = tid & 31;
    int r = lane >> 2, cq = lane & 3;

    int qt = blockIdx.x, bh = blockIdx.y, dir = blockIdx.z;
    int b = bh >> 3, h = bh & 7;
    int enc_q = dir, enc_kv = 1 - dir;

    size_t qoff  = ((size_t)((enc_q *B_ + b)*H_ + h))*L_*HD_;
    size_t kvoff = ((size_t)((enc_kv*B_ + b)*H_ + h))*L_*HD_;
    const unsigned short* Qh = g_qh + qoff;
    const unsigned short* Ql = g_ql + qoff;
    const unsigned short* Kh = g_kh + kvoff;
    const unsigned short* Vh = g_vh + kvoff;
    const unsigned short* mb = g_mb + ((size_t)dir*B_ + b)*L_*L_;
    int q0 = qt * 128;

    #pragma unroll
    for (int i = 0; i < 16; i++) {
        int idx = i*128 + tid;
        int a = idx >> 10;
        int rem = idx & 1023;
        int row = rem >> 3, q8 = rem & 7;
        const unsigned short* srcp = a ? Ql : Qh;
        CP_ASYNC16(sbase + (a ? AT_QL : AT_Q) + row*144 + q8*16,
                   &srcp[(size_t)(q0+row)*HD_ + q8*8]);
    }
    CP_COMMIT();

    auto issue_kv = [&](int t, uint32_t bufo) {
        int k0 = t * 64;
        #pragma unroll
        for (int i = 0; i < 8; i++) {
            int idx = i*128 + tid;
            int a = idx >> 9;
            int rem = idx & 511;
            int row = rem >> 3, q8 = rem & 7;
            const unsigned short* srcp = a ? Vh : Kh;
            int dsto = a ? AT_VH : AT_KH;
            CP_ASYNC16(sbase + bufo + dsto + row*144 + q8*16,
                       &srcp[(size_t)(k0+row)*HD_ + q8*8]);
        }
        CP_COMMIT();
    };

    issue_kv(0, 0);

    float o_acc[2][8][4];
    #pragma unroll
    for (int mt = 0; mt < 2; mt++)
        #pragma unroll
        for (int nt = 0; nt < 8; nt++)
            #pragma unroll
            for (int c = 0; c < 4; c++) o_acc[mt][nt][c] = 0.f;
    float mreg[2][2], lreg[2][2];
    #pragma unroll
    for (int mt = 0; mt < 2; mt++) {
        mreg[mt][0] = -3.0e38f; mreg[mt][1] = -3.0e38f;
        lreg[mt][0] = 0.f;      lreg[mt][1] = 0.f;
    }

    int qgw = q0 + wid*32 + r;
    const unsigned short* mbrow[2][2];
    #pragma unroll
    for (int mt = 0; mt < 2; mt++) {
        mbrow[mt][0] = mb + (size_t)(qgw + mt*16)*L_ + cq*2;
        mbrow[mt][1] = mb + (size_t)(qgw + mt*16 + 8)*L_ + cq*2;
    }

    for (int t = 0; t < 16; t++) {
        int k0 = t * 64;
        uint32_t bufo = (t & 1) ? AT_BUF : 0;
        CP_WAIT0();
        __syncthreads();
        if (t + 1 < 16)
            issue_kv(t + 1, ((t + 1) & 1) ? AT_BUF : 0);

        // ---- prefetch mask+bias as raw half2 words (hidden under QK) ----
        uint32_t mbr[2][2][8];
        #pragma unroll
        for (int mt = 0; mt < 2; mt++)
            #pragma unroll
            for (int rp = 0; rp < 2; rp++)
                #pragma unroll
                for (int nt = 0; nt < 8; nt++)
                    mbr[mt][rp][nt] =
                        *(const uint32_t*)&mbrow[mt][rp][k0 + nt*8];

        // ---- S = Q K^T ----
        float s_acc[2][8][4];
        #pragma unroll
        for (int mt = 0; mt < 2; mt++)
            #pragma unroll
            for (int nt = 0; nt < 8; nt++)
                #pragma unroll
                for (int c = 0; c < 4; c++) s_acc[mt][nt][c] = 0.f;

        #pragma unroll
        for (int ks = 0; ks < 4; ks++) {
            uint32_t aq_h[2][4], aq_l[2][4];
            #pragma unroll
            for (int mt = 0; mt < 2; mt++) {
                int row = wid*32 + mt*16 + (lane & 15);
                int kcol = ks*16 + ((lane >> 4) << 3);
                uint32_t qoff2 = (uint32_t)(row*144 + kcol*2);
                ldsm_x4(aq_h[mt][0], aq_h[mt][1], aq_h[mt][2], aq_h[mt][3],
                        sbase + AT_Q + qoff2);
                ldsm_x4(aq_l[mt][0], aq_l[mt][1], aq_l[mt][2], aq_l[mt][3],
                        sbase + AT_QL + qoff2);
            }
            #pragma unroll
            for (int g = 0; g < 4; g++) {
                uint32_t bk[4];
                int rr = lane & 7;
                int hk = (lane >> 3) & 1;
                int hn = (lane >> 4) & 1;
                int nrow = g*16 + hn*8 + rr;
                int kcol = ks*16 + hk*8;
                uint32_t off = bufo + (uint32_t)(nrow*144 + kcol*2);
                ldsm_x4(bk[0], bk[1], bk[2], bk[3], sbase + AT_KH + off);
                int n0t = g*2, n1t = g*2 + 1;
                #pragma unroll
                for (int mt = 0; mt < 2; mt++) {
                    mma_f16(s_acc[mt][n0t], aq_h[mt], &bk[0]);
                    mma_f16(s_acc[mt][n1t], aq_h[mt], &bk[2]);
                    mma_f16(s_acc[mt][n0t], aq_l[mt], &bk[0]);
                    mma_f16(s_acc[mt][n1t], aq_l[mt], &bk[2]);
                }
            }
        }

        // ---- mask+bias add + softmax per m-tile ----
        #pragma unroll
        for (int mt = 0; mt < 2; mt++) {
            #pragma unroll
            for (int nt = 0; nt < 8; nt++) {
                float2 b0v = h2unpack(mbr[mt][0][nt]);
                float2 b1v = h2unpack(mbr[mt][1][nt]);
                s_acc[mt][nt][0] += b0v.x;
                s_acc[mt][nt][1] += b0v.y;
                s_acc[mt][nt][2] += b1v.x;
                s_acc[mt][nt][3] += b1v.y;
            }

            float mx0 = -3.0e38f, mx1 = -3.0e38f;
            #pragma unroll
            for (int nt = 0; nt < 8; nt++) {
                mx0 = fmaxf(mx0, fmaxf(s_acc[mt][nt][0], s_acc[mt][nt][1]));
                mx1 = fmaxf(mx1, fmaxf(s_acc[mt][nt][2], s_acc[mt][nt][3]));
            }
            mx0 = fmaxf(mx0, __shfl_xor_sync(0xffffffffu, mx0, 1));
            mx0 = fmaxf(mx0, __shfl_xor_sync(0xffffffffu, mx0, 2));
            mx1 = fmaxf(mx1, __shfl_xor_sync(0xffffffffu, mx1, 1));
            mx1 = fmaxf(mx1, __shfl_xor_sync(0xffffffffu, mx1, 2));

            float mn0 = fmaxf(mreg[mt][0], mx0);
            float mn1 = fmaxf(mreg[mt][1], mx1);
            float c0 = ex2f(mreg[mt][0] - mn0);
            float c1 = ex2f(mreg[mt][1] - mn1);
            mreg[mt][0] = mn0; mreg[mt][1] = mn1;

            float rs0 = 0.f, rs1 = 0.f;
            #pragma unroll
            for (int nt = 0; nt < 8; nt++) {
                s_acc[mt][nt][0] = ex2f(s_acc[mt][nt][0] - mn0); rs0 += s_acc[mt][nt][0];
                s_acc[mt][nt][1] = ex2f(s_acc[mt][nt][1] - mn0); rs0 += s_acc[mt][nt][1];
                s_acc[mt][nt][2] = ex2f(s_acc[mt][nt][2] - mn1); rs1 += s_acc[mt][nt][2];
                s_acc[mt][nt][3] = ex2f(s_acc[mt][nt][3] - mn1); rs1 += s_acc[mt][nt][3];
            }
            rs0 += __shfl_xor_sync(0xffffffffu, rs0, 1);
            rs0 += __shfl_xor_sync(0xffffffffu, rs0, 2);
            rs1 += __shfl_xor_sync(0xffffffffu, rs1, 1);
            rs1 += __shfl_xor_sync(0xffffffffu, rs1, 2);
            lreg[mt][0] = lreg[mt][0]*c0 + rs0;
            lreg[mt][1] = lreg[mt][1]*c1 + rs1;

            #pragma unroll
            for (int nt = 0; nt < 8; nt++) {
                o_acc[mt][nt][0] *= c0; o_acc[mt][nt][1] *= c0;
                o_acc[mt][nt][2] *= c1; o_acc[mt][nt][3] *= c1;
            }
        }

        // ---- O += P V ----
        #pragma unroll
        for (int ks = 0; ks < 4; ks++) {
            int t0 = 2*ks, t1 = 2*ks + 1;
            uint32_t ap[2][4];
            #pragma unroll
            for (int mt = 0; mt < 2; mt++) {
                ap[mt][0] = pack2h(s_acc[mt][t0][0], s_acc[mt][t0][1]);
                ap[mt][1] = pack2h(s_acc[mt][t0][2], s_acc[mt][t0][3]);
                ap[mt][2] = pack2h(s_acc[mt][t1][0], s_acc[mt][t1][1]);
                ap[mt][3] = pack2h(s_acc[mt][t1][2], s_acc[mt][t1][3]);
            }
            #pragma unroll
            for (int g = 0; g < 4; g++) {
                uint32_t bv[4];
                int kk  = ks*16 + ((lane >> 3) & 1)*8 + (lane & 7);
                int hdo = g*16 + ((lane >> 4) & 1)*8;
                uint32_t off = bufo + (uint32_t)(kk*144 + hdo*2);
                ldsm_x4_t(bv[0], bv[1], bv[2], bv[3], sbase + AT_VH + off);
                int n0t = g*2, n1t = g*2 + 1;
                #pragma unroll
                for (int mt = 0; mt < 2; mt++) {
                    mma_f16(o_acc[mt][n0t], ap[mt], &bv[0]);
                    mma_f16(o_acc[mt][n1t], ap[mt], &bv[2]);
                }
            }
        }
    }

    // ---- finalize: ctx = O/l as single fp16 ----
    #pragma unroll
    for (int mt = 0; mt < 2; mt++) {
        float inv0 = 1.f / lreg[mt][0];
        float inv1 = 1.f / lreg[mt][1];
        int row0g = qgw + mt*16;
        size_t base0 = ((size_t)(enc_q*B_ + b)*L_ + row0g)*D_ + h*64 + cq*2;
        size_t base1 = ((size_t)(enc_q*B_ + b)*L_ + row0g + 8)*D_ + h*64 + cq*2;
        #pragma unroll
        for (int nt = 0; nt < 8; nt++) {
            *(uint32_t*)&g_ch[base0 + nt*8] =
                pack2h(o_acc[mt][nt][0]*inv0, o_acc[mt][nt][1]*inv0);
            *(uint32_t*)&g_ch[base1 + nt*8] =
                pack2h(o_acc[mt][nt][2]*inv1, o_acc[mt][nt][3]*inv1);
        }
    }
}

// ---------------------------------------------------------------------------
extern "C" void kernel_launch(void* const* d_in, const int* in_sizes, int n_in,
                              void* d_out, int out_size)
{
    const float* u_enc     = (const float*)d_in[0];
    const float* e_enc     = (const float*)d_in[1];
    const float* logit_bpp = (const float*)d_in[2];
    const void*  ue_mask   = d_in[3];
    const void*  eu_mask   = d_in[4];
    const float* wq_k = (const float*)d_in[5];
    const float* wq_b = (const float*)d_in[6];
    const float* wk_k = (const float*)d_in[7];
    const float* wk_b = (const float*)d_in[8];
    const float* wv_k = (const float*)d_in[9];
    const float* wv_b = (const float*)d_in[10];
    const float* wo_k = (const float*)d_in[11];
    const float* wo_b = (const float*)d_in[12];
    const float* bpp_w = (const float*)d_in[13];
    const float* bpp_b = (const float*)d_in[14];
    float* out = (float*)d_out;

    cudaFuncSetAttribute((const void*)attn_mma_kernel,
                         cudaFuncAttributeMaxDynamicSharedMemorySize, AT_SMEM);
    cudaFuncSetAttribute((const void*)qkv_mma_kernel,
                         cudaFuncAttributeMaxDynamicSharedMemorySize, QG_SMEM);
    cudaFuncSetAttribute((const void*)oproj_mma_kernel,
                         cudaFuncAttributeMaxDynamicSharedMemorySize, GM_SMEM);

    // 0) mask dtype detection
    mask_detect_kernel<<<1, 256>>>((const unsigned int*)ue_mask);
    // 1) fused prep
    prep_kernel<<<5120, 256>>>(logit_bpp, bpp_w, bpp_b, ue_mask, eu_mask,
                               u_enc, e_enc, wq_k, wk_k, wv_k, wo_k);
    // 2) fused QKV projection
    qkv_mma_kernel<<<dim3(8, 64), 256, QG_SMEM>>>(wq_b, wk_b, wv_b);
    // 3) fused attention -> ctx single fp16
    attn_mma_kernel<<<dim3(8, 32, 2), 128, AT_SMEM>>>();
    // 4) output projection (1-term) -> d_out
    oproj_mma_kernel<<<dim3(8, 64), 256, GM_SMEM>>>(wo_b, out);
}